// round 1
// baseline (speedup 1.0000x reference)
#include <cuda_runtime.h>
#include <math.h>

#define BSZ   2048
#define DIMV  200
#define NENT  100000
#define NTS   400
#define EPSV  1e-5f
#define REG_OFF 204800000L
#define T_OFF   204800005L

// ---------------- device-global scratch (no allocations allowed) ----------------
__device__ __align__(16) float g_lhs[BSZ * DIMV];     // lhs [b][d]
__device__ __align__(16) float g_reltT[DIMV * BSZ];   // rel*time transposed [k][b]
__device__ __align__(16) float g_lhsnT[DIMV * BSZ];   // bn0(lhs) transposed [d][b]
__device__ __align__(16) float g_h[BSZ * DIMV];       // h [b][e]
__device__ __align__(16) float g_hnT[DIMV * BSZ];     // bn1(h) transposed [d][b]
__device__ float g_sum0[DIMV], g_sq0[DIMV], g_sum1[DIMV], g_sq1[DIMV];
__device__ float g_scale0[DIMV], g_shift0[DIMV], g_scale1[DIMV], g_shift1[DIMV];
__device__ float g_acc[8];       // norm4 accumulators: 0 lhs_n, 1 rel*t, 2 rel_noT, 3 rhs, 4 w
__device__ int   g_idx64;

// ---------------- K0: zero accumulators + detect index width ----------------
__global__ void k_init(const int* __restrict__ xraw) {
    int i = blockIdx.x * blockDim.x + threadIdx.x;
    int stride = gridDim.x * blockDim.x;
    for (int j = i; j < BSZ * DIMV; j += stride) g_h[j] = 0.f;
    if (i < DIMV) { g_sum0[i] = 0.f; g_sq0[i] = 0.f; g_sum1[i] = 0.f; g_sq1[i] = 0.f; }
    if (i < 8) g_acc[i] = 0.f;
    if (i == 0) {
        // int64 little-endian with values < 400 -> all odd 32-bit words are zero.
        // For int32 these words are 8 random values in [0,400): P(all zero) ~ 400^-8.
        int odd = xraw[1] | xraw[3] | xraw[5] | xraw[7] |
                  xraw[9] | xraw[11] | xraw[13] | xraw[15];
        g_idx64 = (odd == 0) ? 1 : 0;
    }
}

// ---------------- K1: gather + BN0 stats + reg norms 1..3 ----------------
__global__ void k_gather(const int* __restrict__ x32,
                         const float* __restrict__ E,
                         const float* __restrict__ R,
                         const float* __restrict__ RnoT,
                         const float* __restrict__ T) {
    __shared__ int sidx[4];
    __shared__ float sr[3][8];
    int b = blockIdx.x, t = threadIdx.x;
    if (t < 4) {
        int v;
        if (g_idx64) { const long long* x64 = (const long long*)x32; v = (int)x64[(long)b * 4 + t]; }
        else         { v = x32[b * 4 + t]; }
        sidx[t] = v;
    }
    __syncthreads();
    int x0 = sidx[0], x1 = sidx[1], x2 = sidx[2], x3 = sidx[3];
    float p1 = 0.f, p2 = 0.f, p3 = 0.f;
    if (t < DIMV) {
        float lv = E[(long)x0 * DIMV + t];
        float rv = R[x1 * DIMV + t];
        float tv = T[x3 * DIMV + t];
        float rt = rv * tv;
        g_lhs[b * DIMV + t] = lv;
        g_reltT[t * BSZ + b] = rt;
        atomicAdd(&g_sum0[t], lv);
        atomicAdd(&g_sq0[t], lv * lv);
        float rn = RnoT[x1 * DIMV + t];
        float rh = E[(long)x2 * DIMV + t];
        float a = rt * rt;  p1 = a * a;
        float c = rn * rn;  p2 = c * c;
        float e2 = rh * rh; p3 = e2 * e2;
    }
    #pragma unroll
    for (int o = 16; o > 0; o >>= 1) {
        p1 += __shfl_down_sync(0xffffffffu, p1, o);
        p2 += __shfl_down_sync(0xffffffffu, p2, o);
        p3 += __shfl_down_sync(0xffffffffu, p3, o);
    }
    int lane = t & 31, w = t >> 5;
    if (lane == 0) { sr[0][w] = p1; sr[1][w] = p2; sr[2][w] = p3; }
    __syncthreads();
    if (t == 0) {
        float s1 = 0.f, s2 = 0.f, s3 = 0.f;
        for (int i = 0; i < 8; i++) { s1 += sr[0][i]; s2 += sr[1][i]; s3 += sr[2][i]; }
        atomicAdd(&g_acc[1], s1);
        atomicAdd(&g_acc[2], s2);
        atomicAdd(&g_acc[3], s3);
    }
}

// ---------------- K2/K6: fold BN stats into scale/shift ----------------
__global__ void k_finalize(const float* __restrict__ gamma,
                           const float* __restrict__ beta, int which) {
    int d = threadIdx.x;
    if (d >= DIMV) return;
    float s = which ? g_sum1[d] : g_sum0[d];
    float q = which ? g_sq1[d]  : g_sq0[d];
    float mean = s * (1.f / BSZ);
    float var  = q * (1.f / BSZ) - mean * mean;
    float inv  = rsqrtf(var + EPSV);
    float sc   = gamma[d] * inv;
    float sh   = beta[d] - mean * sc;
    if (which) { g_scale1[d] = sc; g_shift1[d] = sh; }
    else       { g_scale0[d] = sc; g_shift0[d] = sh; }
}

// ---------------- K3: lhs_n (transposed) + reg norm 0 ----------------
__global__ void k_norm0() {
    __shared__ float sb[8];
    int b = blockIdx.x, t = threadIdx.x;
    float p = 0.f;
    if (t < DIMV) {
        float v = g_lhs[b * DIMV + t] * g_scale0[t] + g_shift0[t];
        g_lhsnT[t * BSZ + b] = v;
        float a = v * v; p = a * a;
    }
    #pragma unroll
    for (int o = 16; o > 0; o >>= 1) p += __shfl_down_sync(0xffffffffu, p, o);
    int lane = t & 31, w = t >> 5;
    if (lane == 0) sb[w] = p;
    __syncthreads();
    if (t == 0) {
        float s = 0.f;
        for (int i = 0; i < 8; i++) s += sb[i];
        atomicAdd(&g_acc[0], s);
    }
}

// ---------------- K4: h = (relt ⊗ lhs_n) · W   (A generated on the fly) ----------------
// C(2048x200) = A(2048x40000) * W2(40000x200), A[b, k*200+d] = relt[b,k]*lhsn[b,d]
// Tile: 64(b) x 200(e), 200 threads, 8x8 micro-tile, K-split over k in grid.y.
__global__ __launch_bounds__(200) void k_hgemm(const float* __restrict__ W) {
    __shared__ __align__(16) float As[8][64];
    __shared__ __align__(16) float Bs[8][DIMV];
    const int t  = threadIdx.x;
    const int tx = t % 25;        // e-tile: 25 * 8 = 200
    const int ty = t / 25;        // b-tile: 8 * 8 = 64
    const int b0 = blockIdx.x * 64;
    const int kbeg = blockIdx.y * 10;
    float4 acc[8][2];
    #pragma unroll
    for (int m = 0; m < 8; m++) {
        acc[m][0] = make_float4(0.f, 0.f, 0.f, 0.f);
        acc[m][1] = make_float4(0.f, 0.f, 0.f, 0.f);
    }
    for (int k = kbeg; k < kbeg + 10; k++) {
        const float* __restrict__ rrow = &g_reltT[k * BSZ + b0];
        for (int dc = 0; dc < DIMV; dc += 8) {
            __syncthreads();
            for (int i = t; i < 8 * 64; i += 200) {
                int j = i >> 6, bb = i & 63;
                As[j][bb] = rrow[bb] * g_lhsnT[(dc + j) * BSZ + b0 + bb];
            }
            const float* __restrict__ wp = W + ((long)k * DIMV + dc) * DIMV;
            for (int i = t; i < 8 * DIMV; i += 200) {
                int j = i / DIMV, e = i - j * DIMV;
                Bs[j][e] = wp[j * DIMV + e];
            }
            __syncthreads();
            #pragma unroll
            for (int j = 0; j < 8; j++) {
                float4 A0 = *(const float4*)&As[j][ty * 8];
                float4 A1 = *(const float4*)&As[j][ty * 8 + 4];
                float4 B0 = *(const float4*)&Bs[j][tx * 8];
                float4 B1 = *(const float4*)&Bs[j][tx * 8 + 4];
                float am[8] = {A0.x, A0.y, A0.z, A0.w, A1.x, A1.y, A1.z, A1.w};
                #pragma unroll
                for (int m = 0; m < 8; m++) {
                    acc[m][0].x += am[m] * B0.x; acc[m][0].y += am[m] * B0.y;
                    acc[m][0].z += am[m] * B0.z; acc[m][0].w += am[m] * B0.w;
                    acc[m][1].x += am[m] * B1.x; acc[m][1].y += am[m] * B1.y;
                    acc[m][1].z += am[m] * B1.z; acc[m][1].w += am[m] * B1.w;
                }
            }
        }
    }
    #pragma unroll
    for (int m = 0; m < 8; m++) {
        int gb = b0 + ty * 8 + m;
        float* hp = &g_h[gb * DIMV + tx * 8];
        atomicAdd(hp + 0, acc[m][0].x); atomicAdd(hp + 1, acc[m][0].y);
        atomicAdd(hp + 2, acc[m][0].z); atomicAdd(hp + 3, acc[m][0].w);
        atomicAdd(hp + 4, acc[m][1].x); atomicAdd(hp + 5, acc[m][1].y);
        atomicAdd(hp + 6, acc[m][1].z); atomicAdd(hp + 7, acc[m][1].w);
    }
}

// ---------------- K5: BN1 stats over h ----------------
__global__ void k_stats1() {
    int b = blockIdx.x, t = threadIdx.x;
    if (t < DIMV) {
        float v = g_h[b * DIMV + t];
        atomicAdd(&g_sum1[t], v);
        atomicAdd(&g_sq1[t], v * v);
    }
}

// ---------------- K6b: h_n transposed ----------------
__global__ void k_norm1T() {
    int b = blockIdx.x, t = threadIdx.x;
    if (t < DIMV)
        g_hnT[t * BSZ + b] = g_h[b * DIMV + t] * g_scale1[t] + g_shift1[t];
}

// ---------------- K7: pred = h_n @ E^T   (M=2048, N=100000, K=200) ----------------
// Tile 128(b) x 128(e), 256 threads, 8x8 micro-tile, n mapped as tx*4 / tx*4+64
// so every warp's epilogue stores are contiguous 16B chunks.
__global__ __launch_bounds__(256) void k_pred(const float* __restrict__ E,
                                              float* __restrict__ out) {
    __shared__ __align__(16) float As[8][128];
    __shared__ __align__(16) float Bs[8][132];
    const int t  = threadIdx.x;
    const int tx = t & 15;
    const int ty = t >> 4;
    const int b0 = blockIdx.x * 128;   // x = b-tile so consecutive blocks share the E tile (L2 reuse)
    const int e0 = blockIdx.y * 128;
    float4 acc[8][2];
    #pragma unroll
    for (int m = 0; m < 8; m++) {
        acc[m][0] = make_float4(0.f, 0.f, 0.f, 0.f);
        acc[m][1] = make_float4(0.f, 0.f, 0.f, 0.f);
    }
    for (int dc = 0; dc < DIMV; dc += 8) {
        __syncthreads();
        {   // stage h_n tile [8][128] (coalesced from transposed layout)
            int j = t >> 5;
            int b4 = (t & 31) << 2;
            *(float4*)&As[j][b4] = *(const float4*)&g_hnT[(dc + j) * BSZ + b0 + b4];
        }
        {   // stage E tile transposed: Bs[k][e]
            int e = t >> 1, half = t & 1;
            int ge = e0 + e;
            float4 v = make_float4(0.f, 0.f, 0.f, 0.f);
            if (ge < NENT) v = *(const float4*)&E[(long)ge * DIMV + dc + half * 4];
            Bs[half * 4 + 0][e] = v.x; Bs[half * 4 + 1][e] = v.y;
            Bs[half * 4 + 2][e] = v.z; Bs[half * 4 + 3][e] = v.w;
        }
        __syncthreads();
        #pragma unroll
        for (int j = 0; j < 8; j++) {
            float4 A0 = *(const float4*)&As[j][ty * 8];
            float4 A1 = *(const float4*)&As[j][ty * 8 + 4];
            float4 B0 = *(const float4*)&Bs[j][tx * 4];
            float4 B1 = *(const float4*)&Bs[j][tx * 4 + 64];
            float am[8] = {A0.x, A0.y, A0.z, A0.w, A1.x, A1.y, A1.z, A1.w};
            #pragma unroll
            for (int m = 0; m < 8; m++) {
                acc[m][0].x += am[m] * B0.x; acc[m][0].y += am[m] * B0.y;
                acc[m][0].z += am[m] * B0.z; acc[m][0].w += am[m] * B0.w;
                acc[m][1].x += am[m] * B1.x; acc[m][1].y += am[m] * B1.y;
                acc[m][1].z += am[m] * B1.z; acc[m][1].w += am[m] * B1.w;
            }
        }
    }
    #pragma unroll
    for (int m = 0; m < 8; m++) {
        int gb = b0 + ty * 8 + m;
        long row = (long)gb * NENT;
        int e1 = e0 + tx * 4;
        if (e1 < NENT) *(float4*)&out[row + e1] = acc[m][0];
        int e2 = e1 + 64;
        if (e2 < NENT) *(float4*)&out[row + e2] = acc[m][1];
    }
}

// ---------------- K8: norm4 of full W ----------------
__global__ void k_wnorm(const float* __restrict__ W) {
    __shared__ float sb[8];
    long i = blockIdx.x * blockDim.x + threadIdx.x;
    long stride = (long)gridDim.x * blockDim.x;
    float p = 0.f;
    for (long j = i; j < 8000000L; j += stride) {
        float w = W[j]; float a = w * w; p += a * a;
    }
    #pragma unroll
    for (int o = 16; o > 0; o >>= 1) p += __shfl_down_sync(0xffffffffu, p, o);
    int lane = threadIdx.x & 31, w = threadIdx.x >> 5;
    if (lane == 0) sb[w] = p;
    __syncthreads();
    if (threadIdx.x == 0) {
        float s = 0.f;
        for (int k = 0; k < 8; k++) s += sb[k];
        atomicAdd(&g_acc[4], s);
    }
}

// ---------------- K9: reg outputs + T passthrough ----------------
__global__ void k_tail(const float* __restrict__ T, float* __restrict__ out) {
    int i = blockIdx.x * blockDim.x + threadIdx.x;
    if (i < 5) out[REG_OFF + i] = powf(g_acc[i], 0.25f);
    if (i < NTS * DIMV) out[T_OFF + i] = T[i];
}

// ---------------- launch ----------------
extern "C" void kernel_launch(void* const* d_in, const int* in_sizes, int n_in,
                              void* d_out, int out_size) {
    const int*   x    = (const int*)d_in[0];
    const float* E    = (const float*)d_in[1];
    const float* R    = (const float*)d_in[2];
    const float* RnoT = (const float*)d_in[3];
    const float* T    = (const float*)d_in[4];
    const float* W    = (const float*)d_in[5];
    const float* g0   = (const float*)d_in[6];
    const float* be0  = (const float*)d_in[7];
    const float* g1   = (const float*)d_in[8];
    const float* be1  = (const float*)d_in[9];
    float* out = (float*)d_out;

    k_init<<<512, 256>>>(x);
    k_gather<<<BSZ, 256>>>(x, E, R, RnoT, T);
    k_finalize<<<1, 256>>>(g0, be0, 0);
    k_norm0<<<BSZ, 256>>>();
    k_hgemm<<<dim3(32, 20), 200>>>(W);
    k_stats1<<<BSZ, 256>>>();
    k_finalize<<<1, 256>>>(g1, be1, 1);
    k_norm1T<<<BSZ, 256>>>();
    k_pred<<<dim3(16, 782), 256>>>(E, out);
    k_wnorm<<<1024, 256>>>(W);
    k_tail<<<320, 256>>>(T, out);
}

// round 2
// speedup vs baseline: 1.1582x; 1.1582x over previous
#include <cuda_runtime.h>
#include <cuda_bf16.h>
#include <math.h>
#include <stdint.h>

#define BSZ   2048
#define DIMV  200
#define NENT  100000
#define NTS   400
#define EPSV  1e-5f
#define REG_OFF 204800000L
#define T_OFF   204800005L

// ---------------- device-global scratch (no allocations allowed) ----------------
__device__ __align__(16) float g_lhs[BSZ * DIMV];     // lhs [b][d]
__device__ __align__(16) float g_reltT[DIMV * BSZ];   // rel*time transposed [k][b]
__device__ __align__(16) float g_lhsnT[DIMV * BSZ];   // bn0(lhs) transposed [d][b]
__device__ __align__(16) float g_h[BSZ * DIMV];       // h [b][e]
__device__ __align__(16) float g_hn[BSZ * DIMV];      // bn1(h) row-major [b][d]
__device__ float g_sum0[DIMV], g_sq0[DIMV], g_sum1[DIMV], g_sq1[DIMV];
__device__ float g_scale0[DIMV], g_shift0[DIMV], g_scale1[DIMV], g_shift1[DIMV];
__device__ float g_acc[8];       // norm4 accumulators: 0 lhs_n, 1 rel*t, 2 rel_noT, 3 rhs, 4 w
__device__ int   g_idx64;

// ---------------- K0: zero accumulators + detect index width ----------------
__global__ void k_init(const int* __restrict__ xraw) {
    int i = blockIdx.x * blockDim.x + threadIdx.x;
    int stride = gridDim.x * blockDim.x;
    for (int j = i; j < BSZ * DIMV; j += stride) g_h[j] = 0.f;
    if (i < DIMV) { g_sum0[i] = 0.f; g_sq0[i] = 0.f; g_sum1[i] = 0.f; g_sq1[i] = 0.f; }
    if (i < 8) g_acc[i] = 0.f;
    if (i == 0) {
        // int64 little-endian with values < 400 -> all odd 32-bit words are zero.
        int odd = xraw[1] | xraw[3] | xraw[5] | xraw[7] |
                  xraw[9] | xraw[11] | xraw[13] | xraw[15];
        g_idx64 = (odd == 0) ? 1 : 0;
    }
}

// ---------------- K1: gather + BN0 stats + reg norms 1..3 ----------------
__global__ void k_gather(const int* __restrict__ x32,
                         const float* __restrict__ E,
                         const float* __restrict__ R,
                         const float* __restrict__ RnoT,
                         const float* __restrict__ T) {
    __shared__ int sidx[4];
    __shared__ float sr[3][8];
    int b = blockIdx.x, t = threadIdx.x;
    if (t < 4) {
        int v;
        if (g_idx64) { const long long* x64 = (const long long*)x32; v = (int)x64[(long)b * 4 + t]; }
        else         { v = x32[b * 4 + t]; }
        sidx[t] = v;
    }
    __syncthreads();
    int x0 = sidx[0], x1 = sidx[1], x2 = sidx[2], x3 = sidx[3];
    float p1 = 0.f, p2 = 0.f, p3 = 0.f;
    if (t < DIMV) {
        float lv = E[(long)x0 * DIMV + t];
        float rv = R[x1 * DIMV + t];
        float tv = T[x3 * DIMV + t];
        float rt = rv * tv;
        g_lhs[b * DIMV + t] = lv;
        g_reltT[t * BSZ + b] = rt;
        atomicAdd(&g_sum0[t], lv);
        atomicAdd(&g_sq0[t], lv * lv);
        float rn = RnoT[x1 * DIMV + t];
        float rh = E[(long)x2 * DIMV + t];
        float a = rt * rt;  p1 = a * a;
        float c = rn * rn;  p2 = c * c;
        float e2 = rh * rh; p3 = e2 * e2;
    }
    #pragma unroll
    for (int o = 16; o > 0; o >>= 1) {
        p1 += __shfl_down_sync(0xffffffffu, p1, o);
        p2 += __shfl_down_sync(0xffffffffu, p2, o);
        p3 += __shfl_down_sync(0xffffffffu, p3, o);
    }
    int lane = t & 31, w = t >> 5;
    if (lane == 0) { sr[0][w] = p1; sr[1][w] = p2; sr[2][w] = p3; }
    __syncthreads();
    if (t == 0) {
        float s1 = 0.f, s2 = 0.f, s3 = 0.f;
        for (int i = 0; i < 8; i++) { s1 += sr[0][i]; s2 += sr[1][i]; s3 += sr[2][i]; }
        atomicAdd(&g_acc[1], s1);
        atomicAdd(&g_acc[2], s2);
        atomicAdd(&g_acc[3], s3);
    }
}

// ---------------- K2/K6: fold BN stats into scale/shift ----------------
__global__ void k_finalize(const float* __restrict__ gamma,
                           const float* __restrict__ beta, int which) {
    int d = threadIdx.x;
    if (d >= DIMV) return;
    float s = which ? g_sum1[d] : g_sum0[d];
    float q = which ? g_sq1[d]  : g_sq0[d];
    float mean = s * (1.f / BSZ);
    float var  = q * (1.f / BSZ) - mean * mean;
    float inv  = rsqrtf(var + EPSV);
    float sc   = gamma[d] * inv;
    float sh   = beta[d] - mean * sc;
    if (which) { g_scale1[d] = sc; g_shift1[d] = sh; }
    else       { g_scale0[d] = sc; g_shift0[d] = sh; }
}

// ---------------- K3: lhs_n (transposed) + reg norm 0 ----------------
__global__ void k_norm0() {
    __shared__ float sb[8];
    int b = blockIdx.x, t = threadIdx.x;
    float p = 0.f;
    if (t < DIMV) {
        float v = g_lhs[b * DIMV + t] * g_scale0[t] + g_shift0[t];
        g_lhsnT[t * BSZ + b] = v;
        float a = v * v; p = a * a;
    }
    #pragma unroll
    for (int o = 16; o > 0; o >>= 1) p += __shfl_down_sync(0xffffffffu, p, o);
    int lane = t & 31, w = t >> 5;
    if (lane == 0) sb[w] = p;
    __syncthreads();
    if (t == 0) {
        float s = 0.f;
        for (int i = 0; i < 8; i++) s += sb[i];
        atomicAdd(&g_acc[0], s);
    }
}

// ---------------- K4: h = (relt ⊗ lhs_n) · W   (A generated on the fly) ----------------
__global__ __launch_bounds__(200) void k_hgemm(const float* __restrict__ W) {
    __shared__ __align__(16) float As[8][64];
    __shared__ __align__(16) float Bs[8][DIMV];
    const int t  = threadIdx.x;
    const int tx = t % 25;        // e-tile: 25 * 8 = 200
    const int ty = t / 25;        // b-tile: 8 * 8 = 64
    const int b0 = blockIdx.x * 64;
    const int kbeg = blockIdx.y * 10;
    float4 acc[8][2];
    #pragma unroll
    for (int m = 0; m < 8; m++) {
        acc[m][0] = make_float4(0.f, 0.f, 0.f, 0.f);
        acc[m][1] = make_float4(0.f, 0.f, 0.f, 0.f);
    }
    for (int k = kbeg; k < kbeg + 10; k++) {
        const float* __restrict__ rrow = &g_reltT[k * BSZ + b0];
        for (int dc = 0; dc < DIMV; dc += 8) {
            __syncthreads();
            for (int i = t; i < 8 * 64; i += 200) {
                int j = i >> 6, bb = i & 63;
                As[j][bb] = rrow[bb] * g_lhsnT[(dc + j) * BSZ + b0 + bb];
            }
            const float* __restrict__ wp = W + ((long)k * DIMV + dc) * DIMV;
            for (int i = t; i < 8 * DIMV; i += 200) {
                int j = i / DIMV, e = i - j * DIMV;
                Bs[j][e] = wp[j * DIMV + e];
            }
            __syncthreads();
            #pragma unroll
            for (int j = 0; j < 8; j++) {
                float4 A0 = *(const float4*)&As[j][ty * 8];
                float4 A1 = *(const float4*)&As[j][ty * 8 + 4];
                float4 B0 = *(const float4*)&Bs[j][tx * 8];
                float4 B1 = *(const float4*)&Bs[j][tx * 8 + 4];
                float am[8] = {A0.x, A0.y, A0.z, A0.w, A1.x, A1.y, A1.z, A1.w};
                #pragma unroll
                for (int m = 0; m < 8; m++) {
                    acc[m][0].x += am[m] * B0.x; acc[m][0].y += am[m] * B0.y;
                    acc[m][0].z += am[m] * B0.z; acc[m][0].w += am[m] * B0.w;
                    acc[m][1].x += am[m] * B1.x; acc[m][1].y += am[m] * B1.y;
                    acc[m][1].z += am[m] * B1.z; acc[m][1].w += am[m] * B1.w;
                }
            }
        }
    }
    #pragma unroll
    for (int m = 0; m < 8; m++) {
        int gb = b0 + ty * 8 + m;
        float* hp = &g_h[gb * DIMV + tx * 8];
        atomicAdd(hp + 0, acc[m][0].x); atomicAdd(hp + 1, acc[m][0].y);
        atomicAdd(hp + 2, acc[m][0].z); atomicAdd(hp + 3, acc[m][0].w);
        atomicAdd(hp + 4, acc[m][1].x); atomicAdd(hp + 5, acc[m][1].y);
        atomicAdd(hp + 6, acc[m][1].z); atomicAdd(hp + 7, acc[m][1].w);
    }
}

// ---------------- K5: BN1 stats over h ----------------
__global__ void k_stats1() {
    int b = blockIdx.x, t = threadIdx.x;
    if (t < DIMV) {
        float v = g_h[b * DIMV + t];
        atomicAdd(&g_sum1[t], v);
        atomicAdd(&g_sq1[t], v * v);
    }
}

// ---------------- K6b: h_n (row-major, for tensor-core A staging) ----------------
__global__ void k_norm1() {
    int b = blockIdx.x, t = threadIdx.x;
    if (t < DIMV)
        g_hn[b * DIMV + t] = g_h[b * DIMV + t] * g_scale1[t] + g_shift1[t];
}

// ---------------- tensor-core helpers ----------------
__device__ __forceinline__ void ldsm_x4(uint32_t& r0, uint32_t& r1, uint32_t& r2, uint32_t& r3,
                                        uint32_t addr) {
    asm volatile("ldmatrix.sync.aligned.m8n8.x4.shared.b16 {%0,%1,%2,%3}, [%4];"
                 : "=r"(r0), "=r"(r1), "=r"(r2), "=r"(r3) : "r"(addr));
}
__device__ __forceinline__ void mma_bf16(float& c0, float& c1, float& c2, float& c3,
                                         uint32_t a0, uint32_t a1, uint32_t a2, uint32_t a3,
                                         uint32_t b0, uint32_t b1) {
    asm volatile("mma.sync.aligned.m16n8k16.row.col.f32.bf16.bf16.f32 "
                 "{%0,%1,%2,%3},{%4,%5,%6,%7},{%8,%9},{%0,%1,%2,%3};"
                 : "+f"(c0), "+f"(c1), "+f"(c2), "+f"(c3)
                 : "r"(a0), "r"(a1), "r"(a2), "r"(a3), "r"(b0), "r"(b1));
}

// ---------------- K7: pred = h_n @ E^T via bf16x3 split MMA ----------------
// Block tile: M=64 (b) x N=128 (e); 256 threads = 8 warps (2 m x 4 n).
// K = 200, padded to 208 = 13 chunks of 16. A,B split into bf16 hi/lo in smem.
// Row stride 24 bf16 (48B): ldmatrix 16B groups land on distinct banks.
#define KPAD 24
__global__ __launch_bounds__(256) void k_pred(const float* __restrict__ E,
                                              float* __restrict__ out) {
    __shared__ __align__(16) __nv_bfloat16 sAh[64 * KPAD];
    __shared__ __align__(16) __nv_bfloat16 sAl[64 * KPAD];
    __shared__ __align__(16) __nv_bfloat16 sBh[128 * KPAD];
    __shared__ __align__(16) __nv_bfloat16 sBl[128 * KPAD];
    const int t    = threadIdx.x;
    const int lane = t & 31;
    const int w    = t >> 5;
    const int wm   = (w & 1) * 32;   // warp m offset within 64
    const int wn   = (w >> 1) * 32;  // warp n offset within 128
    const int b0   = blockIdx.x * 64;
    const int e0   = blockIdx.y * 128;

    const uint32_t uAh = (uint32_t)__cvta_generic_to_shared(sAh);
    const uint32_t uAl = (uint32_t)__cvta_generic_to_shared(sAl);
    const uint32_t uBh = (uint32_t)__cvta_generic_to_shared(sBh);
    const uint32_t uBl = (uint32_t)__cvta_generic_to_shared(sBl);

    float c[2][4][4];
    #pragma unroll
    for (int mi = 0; mi < 2; mi++)
        #pragma unroll
        for (int ni = 0; ni < 4; ni++)
            #pragma unroll
            for (int q = 0; q < 4; q++) c[mi][ni][q] = 0.f;

    for (int kc = 0; kc < 208; kc += 16) {
        __syncthreads();
        // stage A: 64 rows x 16 k, fp32 -> bf16 hi/lo
        #pragma unroll
        for (int i = t; i < 64 * 16; i += 256) {
            int kk = i & 15, m = i >> 4;
            int gk = kc + kk;
            float v = (gk < DIMV) ? g_hn[(b0 + m) * DIMV + gk] : 0.f;
            __nv_bfloat16 hi = __float2bfloat16(v);
            sAh[m * KPAD + kk] = hi;
            sAl[m * KPAD + kk] = __float2bfloat16(v - __bfloat162float(hi));
        }
        // stage B: 128 rows x 16 k
        #pragma unroll
        for (int i = t; i < 128 * 16; i += 256) {
            int kk = i & 15, e = i >> 4;
            int ge = e0 + e, gk = kc + kk;
            float v = (ge < NENT && gk < DIMV) ? E[(long)ge * DIMV + gk] : 0.f;
            __nv_bfloat16 hi = __float2bfloat16(v);
            sBh[e * KPAD + kk] = hi;
            sBl[e * KPAD + kk] = __float2bfloat16(v - __bfloat162float(hi));
        }
        __syncthreads();

        // A fragments: 2 m16 tiles, hi + lo
        uint32_t ah[2][4], al[2][4];
        {
            int arow_base = wm + (lane & 15);
            int acol = (lane >> 4) * 8;
            #pragma unroll
            for (int mi = 0; mi < 2; mi++) {
                uint32_t off = (uint32_t)(((arow_base + mi * 16) * KPAD + acol) * 2);
                ldsm_x4(ah[mi][0], ah[mi][1], ah[mi][2], ah[mi][3], uAh + off);
                ldsm_x4(al[mi][0], al[mi][1], al[mi][2], al[mi][3], uAl + off);
            }
        }
        // B fragments: 2 pairs of n8 tiles (each x4 covers two tiles), hi + lo
        uint32_t bh[2][4], bl[2][4];
        {
            int r = lane & 7, seg = lane >> 3;
            int brow_in = ((seg & 2) ? 8 : 0) + r;
            int bcol = (seg & 1) * 8;
            #pragma unroll
            for (int p = 0; p < 2; p++) {
                uint32_t off = (uint32_t)(((wn + p * 16 + brow_in) * KPAD + bcol) * 2);
                ldsm_x4(bh[p][0], bh[p][1], bh[p][2], bh[p][3], uBh + off);
                ldsm_x4(bl[p][0], bl[p][1], bl[p][2], bl[p][3], uBl + off);
            }
        }
        // MMAs: hi*hi + hi*lo + lo*hi
        #pragma unroll
        for (int mi = 0; mi < 2; mi++) {
            #pragma unroll
            for (int ni = 0; ni < 4; ni++) {
                int p = ni >> 1, q = (ni & 1) * 2;
                float* cc = c[mi][ni];
                mma_bf16(cc[0], cc[1], cc[2], cc[3],
                         ah[mi][0], ah[mi][1], ah[mi][2], ah[mi][3], bh[p][q], bh[p][q + 1]);
                mma_bf16(cc[0], cc[1], cc[2], cc[3],
                         ah[mi][0], ah[mi][1], ah[mi][2], ah[mi][3], bl[p][q], bl[p][q + 1]);
                mma_bf16(cc[0], cc[1], cc[2], cc[3],
                         al[mi][0], al[mi][1], al[mi][2], al[mi][3], bh[p][q], bh[p][q + 1]);
            }
        }
    }

    // epilogue: C fragment -> out
    #pragma unroll
    for (int mi = 0; mi < 2; mi++) {
        #pragma unroll
        for (int ni = 0; ni < 4; ni++) {
            int r  = b0 + wm + mi * 16 + (lane >> 2);
            int cg = e0 + wn + ni * 8 + (lane & 3) * 2;
            if (cg < NENT) {
                float* cc = c[mi][ni];
                *(float2*)&out[(long)r * NENT + cg]       = make_float2(cc[0], cc[1]);
                *(float2*)&out[(long)(r + 8) * NENT + cg] = make_float2(cc[2], cc[3]);
            }
        }
    }
}

// ---------------- K8: norm4 of full W ----------------
__global__ void k_wnorm(const float* __restrict__ W) {
    __shared__ float sb[8];
    long i = blockIdx.x * blockDim.x + threadIdx.x;
    long stride = (long)gridDim.x * blockDim.x;
    float p = 0.f;
    for (long j = i; j < 8000000L; j += stride) {
        float w = W[j]; float a = w * w; p += a * a;
    }
    #pragma unroll
    for (int o = 16; o > 0; o >>= 1) p += __shfl_down_sync(0xffffffffu, p, o);
    int lane = threadIdx.x & 31, w = threadIdx.x >> 5;
    if (lane == 0) sb[w] = p;
    __syncthreads();
    if (threadIdx.x == 0) {
        float s = 0.f;
        for (int k = 0; k < 8; k++) s += sb[k];
        atomicAdd(&g_acc[4], s);
    }
}

// ---------------- K9: reg outputs + T passthrough ----------------
__global__ void k_tail(const float* __restrict__ T, float* __restrict__ out) {
    int i = blockIdx.x * blockDim.x + threadIdx.x;
    if (i < 5) out[REG_OFF + i] = powf(g_acc[i], 0.25f);
    if (i < NTS * DIMV) out[T_OFF + i] = T[i];
}

// ---------------- launch ----------------
extern "C" void kernel_launch(void* const* d_in, const int* in_sizes, int n_in,
                              void* d_out, int out_size) {
    const int*   x    = (const int*)d_in[0];
    const float* E    = (const float*)d_in[1];
    const float* R    = (const float*)d_in[2];
    const float* RnoT = (const float*)d_in[3];
    const float* T    = (const float*)d_in[4];
    const float* W    = (const float*)d_in[5];
    const float* g0   = (const float*)d_in[6];
    const float* be0  = (const float*)d_in[7];
    const float* g1   = (const float*)d_in[8];
    const float* be1  = (const float*)d_in[9];
    float* out = (float*)d_out;

    k_init<<<512, 256>>>(x);
    k_gather<<<BSZ, 256>>>(x, E, R, RnoT, T);
    k_finalize<<<1, 256>>>(g0, be0, 0);
    k_norm0<<<BSZ, 256>>>();
    k_hgemm<<<dim3(32, 20), 200>>>(W);
    k_stats1<<<BSZ, 256>>>();
    k_finalize<<<1, 256>>>(g1, be1, 1);
    k_norm1<<<BSZ, 256>>>();
    k_pred<<<dim3(32, 782), 256>>>(E, out);
    k_wnorm<<<1024, 256>>>(W);
    k_tail<<<320, 256>>>(T, out);
}

// round 4
// speedup vs baseline: 1.8340x; 1.5835x over previous
#include <cuda_runtime.h>
#include <cuda_bf16.h>
#include <math.h>
#include <stdint.h>

#define BSZ   2048
#define DIMV  200
#define NENT  100000
#define NTS   400
#define EPSV  1e-5f
#define REG_OFF 204800000L
#define T_OFF   204800005L
#define KP    24            // smem row pitch in bf16 (48B)
#define NEPAD 100096        // 782*128
#define KDPAD 208           // DIMV padded to mult of 16 (K of pred GEMM)
#define KWROWS 256          // W-transpose rows padded to N-tile coverage (4 x 64)
#define KBIG  40000         // inner K of hgemm

// ---------------- device-global scratch ----------------
__device__ __align__(16) float g_lhs[BSZ * DIMV];
__device__ __align__(16) float g_reltT[DIMV * BSZ];   // [k][b]
__device__ __align__(16) float g_lhsnT[DIMV * BSZ];   // [d][b]
__device__ __align__(16) float g_h[BSZ * DIMV];
__device__ float g_sum0[DIMV], g_sq0[DIMV], g_sum1[DIMV], g_sq1[DIMV];
__device__ float g_scale0[DIMV], g_shift0[DIMV], g_scale1[DIMV], g_shift1[DIMV];
__device__ float g_acc[8];
__device__ int   g_idx64;
// pre-split bf16 operands
__device__ __align__(16) __nv_bfloat16 gEh[(long)NEPAD * KDPAD];
__device__ __align__(16) __nv_bfloat16 gEl[(long)NEPAD * KDPAD];
__device__ __align__(16) __nv_bfloat16 gWTh[(long)KWROWS * KBIG]; // [e][K]
__device__ __align__(16) __nv_bfloat16 gWTl[(long)KWROWS * KBIG];
__device__ __align__(16) __nv_bfloat16 gAh[BSZ * KDPAD];          // h_n hi
__device__ __align__(16) __nv_bfloat16 gAl[BSZ * KDPAD];          // h_n lo

// ---------------- helpers ----------------
__device__ __forceinline__ void ldsm_x4(uint32_t& r0, uint32_t& r1, uint32_t& r2, uint32_t& r3,
                                        uint32_t addr) {
    asm volatile("ldmatrix.sync.aligned.m8n8.x4.shared.b16 {%0,%1,%2,%3}, [%4];"
                 : "=r"(r0), "=r"(r1), "=r"(r2), "=r"(r3) : "r"(addr));
}
__device__ __forceinline__ void mma_bf16(float& c0, float& c1, float& c2, float& c3,
                                         uint32_t a0, uint32_t a1, uint32_t a2, uint32_t a3,
                                         uint32_t b0, uint32_t b1) {
    asm volatile("mma.sync.aligned.m16n8k16.row.col.f32.bf16.bf16.f32 "
                 "{%0,%1,%2,%3},{%4,%5,%6,%7},{%8,%9},{%0,%1,%2,%3};"
                 : "+f"(c0), "+f"(c1), "+f"(c2), "+f"(c3)
                 : "r"(a0), "r"(a1), "r"(a2), "r"(a3), "r"(b0), "r"(b1));
}
#define CPA16(dst_u32, src_ptr) \
    asm volatile("cp.async.cg.shared.global [%0], [%1], 16;" :: "r"(dst_u32), "l"(src_ptr))
#define CP_COMMIT() asm volatile("cp.async.commit_group;")
#define CP_WAIT1()  asm volatile("cp.async.wait_group 1;")

// ---------------- K0: zero + index width ----------------
__global__ void k_init(const int* __restrict__ xraw) {
    int i = blockIdx.x * blockDim.x + threadIdx.x;
    int stride = gridDim.x * blockDim.x;
    for (int j = i; j < BSZ * DIMV; j += stride) g_h[j] = 0.f;
    if (i < DIMV) { g_sum0[i] = 0.f; g_sq0[i] = 0.f; g_sum1[i] = 0.f; g_sq1[i] = 0.f; }
    if (i < 8) g_acc[i] = 0.f;
    if (i == 0) {
        int odd = xraw[1] | xraw[3] | xraw[5] | xraw[7] |
                  xraw[9] | xraw[11] | xraw[13] | xraw[15];
        g_idx64 = (odd == 0) ? 1 : 0;
    }
}

// ---------------- split E into bf16 hi/lo, padded ----------------
__global__ void k_esplit(const float* __restrict__ E) {
    long idx = (long)blockIdx.x * blockDim.x + threadIdx.x;
    if (idx >= (long)NEPAD * 26) return;
    int row = (int)(idx / 26);
    int c8  = (int)(idx % 26) * 8;
    long o  = (long)row * KDPAD + c8;
    if (row < NENT && c8 < DIMV) {
        const float* p = E + (long)row * DIMV + c8;
        #pragma unroll
        for (int j = 0; j < 8; j++) {
            float v = p[j];
            __nv_bfloat16 hi = __float2bfloat16(v);
            gEh[o + j] = hi;
            gEl[o + j] = __float2bfloat16(v - __bfloat162float(hi));
        }
    } else {
        #pragma unroll
        for (int j = 0; j < 8; j++) { gEh[o + j] = __float2bfloat16(0.f); gEl[o + j] = __float2bfloat16(0.f); }
    }
}

// ---------------- transpose+split W -> gWT[e][K] (256 rows, zero-padded), fused norm4(W) ----------------
__global__ void k_wsplit(const float* __restrict__ W) {
    __shared__ float sT[32][33];
    __shared__ float sr[8];
    int K0 = blockIdx.x * 32;   // 1250 blocks
    int e0 = blockIdx.y * 32;   // 8 blocks -> covers 256 rows
    int tx = threadIdx.x & 31, ty = threadIdx.x >> 5;
    float p4 = 0.f;
    #pragma unroll
    for (int r = 0; r < 4; r++) {
        int Kr = K0 + ty + 8 * r;
        int e  = e0 + tx;
        float v = (e < DIMV) ? W[(long)Kr * DIMV + e] : 0.f;
        sT[ty + 8 * r][tx] = v;
        float a = v * v; p4 += a * a;
    }
    __syncthreads();
    #pragma unroll
    for (int r = 0; r < 4; r++) {
        int ew = e0 + ty + 8 * r;
        if (ew < KWROWS) {
            float v = sT[tx][ty + 8 * r];
            __nv_bfloat16 hi = __float2bfloat16(v);
            long o = (long)ew * KBIG + K0 + tx;
            gWTh[o] = hi;
            gWTl[o] = __float2bfloat16(v - __bfloat162float(hi));
        }
    }
    // norm4 reduce
    #pragma unroll
    for (int o = 16; o > 0; o >>= 1) p4 += __shfl_down_sync(0xffffffffu, p4, o);
    if (tx == 0) sr[ty] = p4;
    __syncthreads();
    if (threadIdx.x == 0) {
        float s = 0.f;
        for (int i = 0; i < 8; i++) s += sr[i];
        atomicAdd(&g_acc[4], s);
    }
}

// ---------------- K1: gather + BN0 stats + reg norms 1..3 ----------------
__global__ void k_gather(const int* __restrict__ x32,
                         const float* __restrict__ E,
                         const float* __restrict__ R,
                         const float* __restrict__ RnoT,
                         const float* __restrict__ T) {
    __shared__ int sidx[4];
    __shared__ float sr[3][8];
    int b = blockIdx.x, t = threadIdx.x;
    if (t < 4) {
        int v;
        if (g_idx64) { const long long* x64 = (const long long*)x32; v = (int)x64[(long)b * 4 + t]; }
        else         { v = x32[b * 4 + t]; }
        sidx[t] = v;
    }
    __syncthreads();
    int x0 = sidx[0], x1 = sidx[1], x2 = sidx[2], x3 = sidx[3];
    float p1 = 0.f, p2 = 0.f, p3 = 0.f;
    if (t < DIMV) {
        float lv = E[(long)x0 * DIMV + t];
        float rv = R[x1 * DIMV + t];
        float tv = T[x3 * DIMV + t];
        float rt = rv * tv;
        g_lhs[b * DIMV + t] = lv;
        g_reltT[t * BSZ + b] = rt;
        atomicAdd(&g_sum0[t], lv);
        atomicAdd(&g_sq0[t], lv * lv);
        float rn = RnoT[x1 * DIMV + t];
        float rh = E[(long)x2 * DIMV + t];
        float a = rt * rt;  p1 = a * a;
        float c = rn * rn;  p2 = c * c;
        float e2 = rh * rh; p3 = e2 * e2;
    }
    #pragma unroll
    for (int o = 16; o > 0; o >>= 1) {
        p1 += __shfl_down_sync(0xffffffffu, p1, o);
        p2 += __shfl_down_sync(0xffffffffu, p2, o);
        p3 += __shfl_down_sync(0xffffffffu, p3, o);
    }
    int lane = t & 31, w = t >> 5;
    if (lane == 0) { sr[0][w] = p1; sr[1][w] = p2; sr[2][w] = p3; }
    __syncthreads();
    if (t == 0) {
        float s1 = 0.f, s2 = 0.f, s3 = 0.f;
        for (int i = 0; i < 8; i++) { s1 += sr[0][i]; s2 += sr[1][i]; s3 += sr[2][i]; }
        atomicAdd(&g_acc[1], s1);
        atomicAdd(&g_acc[2], s2);
        atomicAdd(&g_acc[3], s3);
    }
}

// ---------------- BN fold ----------------
__global__ void k_finalize(const float* __restrict__ gamma,
                           const float* __restrict__ beta, int which) {
    int d = threadIdx.x;
    if (d >= DIMV) return;
    float s = which ? g_sum1[d] : g_sum0[d];
    float q = which ? g_sq1[d]  : g_sq0[d];
    float mean = s * (1.f / BSZ);
    float var  = q * (1.f / BSZ) - mean * mean;
    float inv  = rsqrtf(var + EPSV);
    float sc   = gamma[d] * inv;
    float sh   = beta[d] - mean * sc;
    if (which) { g_scale1[d] = sc; g_shift1[d] = sh; }
    else       { g_scale0[d] = sc; g_shift0[d] = sh; }
}

// ---------------- lhs_n transposed + norm0 ----------------
__global__ void k_norm0() {
    __shared__ float sb[8];
    int b = blockIdx.x, t = threadIdx.x;
    float p = 0.f;
    if (t < DIMV) {
        float v = g_lhs[b * DIMV + t] * g_scale0[t] + g_shift0[t];
        g_lhsnT[t * BSZ + b] = v;
        float a = v * v; p = a * a;
    }
    #pragma unroll
    for (int o = 16; o > 0; o >>= 1) p += __shfl_down_sync(0xffffffffu, p, o);
    int lane = t & 31, w = t >> 5;
    if (lane == 0) sb[w] = p;
    __syncthreads();
    if (t == 0) {
        float s = 0.f;
        for (int i = 0; i < 8; i++) s += sb[i];
        atomicAdd(&g_acc[0], s);
    }
}

// ---------------- K4: h GEMM via bf16x3 MMA ----------------
// C(2048x200) = A(2048x40000) * WT^T ; tile M=128(b) x N=64(e), K-split z=10.
__global__ __launch_bounds__(256) void k_hgemm() {
    __shared__ __align__(16) __nv_bfloat16 sAh[2][128 * KP];
    __shared__ __align__(16) __nv_bfloat16 sAl[2][128 * KP];
    __shared__ __align__(16) __nv_bfloat16 sWh[2][64 * KP];
    __shared__ __align__(16) __nv_bfloat16 sWl[2][64 * KP];
    const int t    = threadIdx.x;
    const int lane = t & 31;
    const int w    = t >> 5;
    const int wm   = (w & 1) * 64;
    const int wn   = (w >> 1) * 16;
    const int b0   = blockIdx.x * 128;
    const int e0   = blockIdx.y * 64;
    const int cbeg = blockIdx.z * 250;     // 2500 chunks / 10

    const uint32_t uAh = (uint32_t)__cvta_generic_to_shared(sAh);
    const uint32_t uAl = (uint32_t)__cvta_generic_to_shared(sAl);
    const uint32_t uWh = (uint32_t)__cvta_generic_to_shared(sWh);
    const uint32_t uWl = (uint32_t)__cvta_generic_to_shared(sWl);
    const uint32_t bufA = 128 * KP * 2;
    const uint32_t bufW = 64 * KP * 2;

    const int warr = t >> 7;
    const int wrow = (t & 127) >> 1;
    const int wch  = (t & 1) * 8;
    const int kk = t & 15;
    const int m4 = t >> 4;

    auto stageW = [&](int buf, int kc) {
        const __nv_bfloat16* src = (warr ? gWTl : gWTh) + (long)(e0 + wrow) * KBIG + kc + wch;
        uint32_t dst = (warr ? uWl : uWh) + buf * bufW + (uint32_t)(wrow * KP + wch) * 2;
        CPA16(dst, src);
    };
    auto stageA = [&](int buf, int kc) {
        int K = kc + kk;
        int k = K / DIMV;
        int d = K - k * DIMV;
        const float* rp = &g_reltT[k * BSZ + b0 + m4 * 8];
        const float* lp = &g_lhsnT[d * BSZ + b0 + m4 * 8];
        #pragma unroll
        for (int g = 0; g < 2; g++) {
            float4 rv = *(const float4*)(rp + g * 4);
            float4 lv = *(const float4*)(lp + g * 4);
            float pr[4] = {rv.x * lv.x, rv.y * lv.y, rv.z * lv.z, rv.w * lv.w};
            #pragma unroll
            for (int j = 0; j < 4; j++) {
                __nv_bfloat16 hi = __float2bfloat16(pr[j]);
                int m = m4 * 8 + g * 4 + j;
                sAh[buf][m * KP + kk] = hi;
                sAl[buf][m * KP + kk] = __float2bfloat16(pr[j] - __bfloat162float(hi));
            }
        }
    };

    float c[4][2][4];
    #pragma unroll
    for (int mi = 0; mi < 4; mi++)
        #pragma unroll
        for (int ni = 0; ni < 2; ni++)
            #pragma unroll
            for (int q = 0; q < 4; q++) c[mi][ni][q] = 0.f;

    stageW(0, cbeg * 16);
    CP_COMMIT();
    stageA(0, cbeg * 16);

    for (int cI = 0; cI < 250; cI++) {
        int buf = cI & 1;
        if (cI + 1 < 250) {
            stageW(buf ^ 1, (cbeg + cI + 1) * 16);
            CP_COMMIT();
            stageA(buf ^ 1, (cbeg + cI + 1) * 16);
        } else {
            CP_COMMIT();
        }
        CP_WAIT1();
        __syncthreads();

        uint32_t aAh = uAh + buf * bufA, aAl = uAl + buf * bufA;
        uint32_t aWh = uWh + buf * bufW, aWl = uWl + buf * bufW;
        uint32_t ah[4][4], al[4][4];
        {
            int arow = wm + (lane & 15);
            int acol = (lane >> 4) * 8;
            #pragma unroll
            for (int mi = 0; mi < 4; mi++) {
                uint32_t off = (uint32_t)(((arow + mi * 16) * KP + acol) * 2);
                ldsm_x4(ah[mi][0], ah[mi][1], ah[mi][2], ah[mi][3], aAh + off);
                ldsm_x4(al[mi][0], al[mi][1], al[mi][2], al[mi][3], aAl + off);
            }
        }
        uint32_t bh[4], bl[4];
        {
            int r = lane & 7, seg = lane >> 3;
            int brow = wn + ((seg & 2) ? 8 : 0) + r;
            int bcol = (seg & 1) * 8;
            uint32_t off = (uint32_t)((brow * KP + bcol) * 2);
            ldsm_x4(bh[0], bh[1], bh[2], bh[3], aWh + off);
            ldsm_x4(bl[0], bl[1], bl[2], bl[3], aWl + off);
        }
        #pragma unroll
        for (int mi = 0; mi < 4; mi++) {
            #pragma unroll
            for (int ni = 0; ni < 2; ni++) {
                int q = ni * 2;
                float* cc = c[mi][ni];
                mma_bf16(cc[0], cc[1], cc[2], cc[3],
                         ah[mi][0], ah[mi][1], ah[mi][2], ah[mi][3], bh[q], bh[q + 1]);
                mma_bf16(cc[0], cc[1], cc[2], cc[3],
                         ah[mi][0], ah[mi][1], ah[mi][2], ah[mi][3], bl[q], bl[q + 1]);
                mma_bf16(cc[0], cc[1], cc[2], cc[3],
                         al[mi][0], al[mi][1], al[mi][2], al[mi][3], bh[q], bh[q + 1]);
            }
        }
        __syncthreads();
    }

    #pragma unroll
    for (int mi = 0; mi < 4; mi++) {
        #pragma unroll
        for (int ni = 0; ni < 2; ni++) {
            int r  = b0 + wm + mi * 16 + (lane >> 2);
            int cg = e0 + wn + ni * 8 + (lane & 3) * 2;
            if (cg < DIMV) {
                float* cc = c[mi][ni];
                atomicAdd(&g_h[r * DIMV + cg], cc[0]);
                atomicAdd(&g_h[r * DIMV + cg + 1], cc[1]);
                atomicAdd(&g_h[(r + 8) * DIMV + cg], cc[2]);
                atomicAdd(&g_h[(r + 8) * DIMV + cg + 1], cc[3]);
            }
        }
    }
}

// ---------------- K5: BN1 stats ----------------
__global__ void k_stats1() {
    int b = blockIdx.x, t = threadIdx.x;
    if (t < DIMV) {
        float v = g_h[b * DIMV + t];
        atomicAdd(&g_sum1[t], v);
        atomicAdd(&g_sq1[t], v * v);
    }
}

// ---------------- K6b: h_n -> bf16 hi/lo split (padded) ----------------
__global__ void k_norm1() {
    int b = blockIdx.x, t = threadIdx.x;
    if (t < KDPAD) {
        float v = (t < DIMV) ? g_h[b * DIMV + t] * g_scale1[t] + g_shift1[t] : 0.f;
        __nv_bfloat16 hi = __float2bfloat16(v);
        gAh[b * KDPAD + t] = hi;
        gAl[b * KDPAD + t] = __float2bfloat16(v - __bfloat162float(hi));
    }
}

// ---------------- K7: pred = h_n @ E^T, bf16x3 MMA, pre-split + cp.async ----------------
__global__ __launch_bounds__(256) void k_pred(float* __restrict__ out) {
    __shared__ __align__(16) __nv_bfloat16 sAh[2][128 * KP];
    __shared__ __align__(16) __nv_bfloat16 sAl[2][128 * KP];
    __shared__ __align__(16) __nv_bfloat16 sBh[2][128 * KP];
    __shared__ __align__(16) __nv_bfloat16 sBl[2][128 * KP];
    const int t    = threadIdx.x;
    const int lane = t & 31;
    const int w    = t >> 5;
    const int wm   = (w & 1) * 64;
    const int wn   = (w >> 1) * 32;
    const int b0   = blockIdx.x * 128;
    const int e0   = blockIdx.y * 128;

    const uint32_t uAh = (uint32_t)__cvta_generic_to_shared(sAh);
    const uint32_t uAl = (uint32_t)__cvta_generic_to_shared(sAl);
    const uint32_t uBh = (uint32_t)__cvta_generic_to_shared(sBh);
    const uint32_t uBl = (uint32_t)__cvta_generic_to_shared(sBl);
    const uint32_t bufSz = 128 * KP * 2;

    const int srow = t >> 1;
    const int sch  = (t & 1) * 8;
    auto stage = [&](int buf, int kc) {
        uint32_t doff = buf * bufSz + (uint32_t)(srow * KP + sch) * 2;
        long aoff = (long)(b0 + srow) * KDPAD + kc + sch;
        long boff = (long)(e0 + srow) * KDPAD + kc + sch;
        CPA16(uAh + doff, gAh + aoff);
        CPA16(uAl + doff, gAl + aoff);
        CPA16(uBh + doff, gEh + boff);
        CPA16(uBl + doff, gEl + boff);
    };

    float c[4][4][4];
    #pragma unroll
    for (int mi = 0; mi < 4; mi++)
        #pragma unroll
        for (int ni = 0; ni < 4; ni++)
            #pragma unroll
            for (int q = 0; q < 4; q++) c[mi][ni][q] = 0.f;

    stage(0, 0);
    CP_COMMIT();

    for (int cI = 0; cI < 13; cI++) {
        int buf = cI & 1;
        if (cI + 1 < 13) stage(buf ^ 1, (cI + 1) * 16);
        CP_COMMIT();
        CP_WAIT1();
        __syncthreads();

        uint32_t aAh = uAh + buf * bufSz, aAl = uAl + buf * bufSz;
        uint32_t aBh = uBh + buf * bufSz, aBl = uBl + buf * bufSz;
        uint32_t ah[4][4], al[4][4];
        {
            int arow = wm + (lane & 15);
            int acol = (lane >> 4) * 8;
            #pragma unroll
            for (int mi = 0; mi < 4; mi++) {
                uint32_t off = (uint32_t)(((arow + mi * 16) * KP + acol) * 2);
                ldsm_x4(ah[mi][0], ah[mi][1], ah[mi][2], ah[mi][3], aAh + off);
                ldsm_x4(al[mi][0], al[mi][1], al[mi][2], al[mi][3], aAl + off);
            }
        }
        uint32_t bh[2][4], bl[2][4];
        {
            int r = lane & 7, seg = lane >> 3;
            int brow_in = ((seg & 2) ? 8 : 0) + r;
            int bcol = (seg & 1) * 8;
            #pragma unroll
            for (int p = 0; p < 2; p++) {
                uint32_t off = (uint32_t)(((wn + p * 16 + brow_in) * KP + bcol) * 2);
                ldsm_x4(bh[p][0], bh[p][1], bh[p][2], bh[p][3], aBh + off);
                ldsm_x4(bl[p][0], bl[p][1], bl[p][2], bl[p][3], aBl + off);
            }
        }
        #pragma unroll
        for (int mi = 0; mi < 4; mi++) {
            #pragma unroll
            for (int ni = 0; ni < 4; ni++) {
                int p = ni >> 1, q = (ni & 1) * 2;
                float* cc = c[mi][ni];
                mma_bf16(cc[0], cc[1], cc[2], cc[3],
                         ah[mi][0], ah[mi][1], ah[mi][2], ah[mi][3], bh[p][q], bh[p][q + 1]);
                mma_bf16(cc[0], cc[1], cc[2], cc[3],
                         ah[mi][0], ah[mi][1], ah[mi][2], ah[mi][3], bl[p][q], bl[p][q + 1]);
                mma_bf16(cc[0], cc[1], cc[2], cc[3],
                         al[mi][0], al[mi][1], al[mi][2], al[mi][3], bh[p][q], bh[p][q + 1]);
            }
        }
        __syncthreads();
    }

    #pragma unroll
    for (int mi = 0; mi < 4; mi++) {
        #pragma unroll
        for (int ni = 0; ni < 4; ni++) {
            int r  = b0 + wm + mi * 16 + (lane >> 2);
            int cg = e0 + wn + ni * 8 + (lane & 3) * 2;
            if (cg < NENT) {
                float* cc = c[mi][ni];
                *(float2*)&out[(long)r * NENT + cg]       = make_float2(cc[0], cc[1]);
                *(float2*)&out[(long)(r + 8) * NENT + cg] = make_float2(cc[2], cc[3]);
            }
        }
    }
}

// ---------------- K9: reg outputs + T passthrough ----------------
__global__ void k_tail(const float* __restrict__ T, float* __restrict__ out) {
    int i = blockIdx.x * blockDim.x + threadIdx.x;
    if (i < 5) out[REG_OFF + i] = powf(g_acc[i], 0.25f);
    if (i < NTS * DIMV) out[T_OFF + i] = T[i];
}

// ---------------- launch ----------------
extern "C" void kernel_launch(void* const* d_in, const int* in_sizes, int n_in,
                              void* d_out, int out_size) {
    const int*   x    = (const int*)d_in[0];
    const float* E    = (const float*)d_in[1];
    const float* R    = (const float*)d_in[2];
    const float* RnoT = (const float*)d_in[3];
    const float* T    = (const float*)d_in[4];
    const float* W    = (const float*)d_in[5];
    const float* g0   = (const float*)d_in[6];
    const float* be0  = (const float*)d_in[7];
    const float* g1   = (const float*)d_in[8];
    const float* be1  = (const float*)d_in[9];
    float* out = (float*)d_out;

    k_init<<<512, 256>>>(x);
    k_esplit<<<(int)(((long)NEPAD * 26 + 255) / 256), 256>>>(E);
    k_wsplit<<<dim3(1250, 8), 256>>>(W);
    k_gather<<<BSZ, 256>>>(x, E, R, RnoT, T);
    k_finalize<<<1, 256>>>(g0, be0, 0);
    k_norm0<<<BSZ, 256>>>();
    k_hgemm<<<dim3(16, 4, 10), 256>>>();
    k_stats1<<<BSZ, 256>>>();
    k_finalize<<<1, 256>>>(g1, be1, 1);
    k_norm1<<<BSZ, 256>>>();
    k_pred<<<dim3(16, 782), 256>>>(out);
    k_tail<<<320, 256>>>(T, out);
}

// round 5
// speedup vs baseline: 2.8947x; 1.5784x over previous
#include <cuda_runtime.h>
#include <cuda_fp16.h>
#include <math.h>
#include <stdint.h>

#define BSZ   2048
#define DIMV  200
#define NENT  100000
#define NTS   400
#define EPSV  1e-5f
#define REG_OFF 204800000L
#define T_OFF   204800005L
#define KP    24            // smem row pitch in halves (48B)
#define NEPAD 100096        // 782*128
#define KDPAD 208           // DIMV padded to mult of 16 (K of pred GEMM)
#define KWROWS 256          // W-transpose rows padded to N-tile coverage (4 x 64)
#define KBIG  40000         // inner K of hgemm

// ---------------- device-global scratch ----------------
__device__ __align__(16) float g_lhsT[DIMV * BSZ];    // lhs transposed [d][b]
__device__ __align__(16) float g_reltT[DIMV * BSZ];   // rel*time [k][b]
__device__ __align__(16) float g_lhsnT[DIMV * BSZ];   // bn0(lhs) [d][b]
__device__ __align__(16) float g_hT[DIMV * BSZ];      // h transposed [e][b]
__device__ float g_acc[8];
__device__ int   g_idx64;
// fp16 operands
__device__ __align__(16) __half gEh[(long)NEPAD * KDPAD];
__device__ __align__(16) __half gWTh[(long)KWROWS * KBIG]; // [e][K]
__device__ __align__(16) __half gAh[BSZ * KDPAD];          // h_n fp16 [b][K]

// ---------------- helpers ----------------
__device__ __forceinline__ void ldsm_x4(uint32_t& r0, uint32_t& r1, uint32_t& r2, uint32_t& r3,
                                        uint32_t addr) {
    asm volatile("ldmatrix.sync.aligned.m8n8.x4.shared.b16 {%0,%1,%2,%3}, [%4];"
                 : "=r"(r0), "=r"(r1), "=r"(r2), "=r"(r3) : "r"(addr));
}
__device__ __forceinline__ void mma_f16(float& c0, float& c1, float& c2, float& c3,
                                        uint32_t a0, uint32_t a1, uint32_t a2, uint32_t a3,
                                        uint32_t b0, uint32_t b1) {
    asm volatile("mma.sync.aligned.m16n8k16.row.col.f32.f16.f16.f32 "
                 "{%0,%1,%2,%3},{%4,%5,%6,%7},{%8,%9},{%0,%1,%2,%3};"
                 : "+f"(c0), "+f"(c1), "+f"(c2), "+f"(c3)
                 : "r"(a0), "r"(a1), "r"(a2), "r"(a3), "r"(b0), "r"(b1));
}
#define CPA16(dst_u32, src_ptr) \
    asm volatile("cp.async.cg.shared.global [%0], [%1], 16;" :: "r"(dst_u32), "l"(src_ptr))
#define CP_COMMIT() asm volatile("cp.async.commit_group;")
#define CP_WAIT1()  asm volatile("cp.async.wait_group 1;")

// ---------------- K0: zero + pad + index width ----------------
__global__ void k_init(const int* __restrict__ xraw) {
    int i = blockIdx.x * blockDim.x + threadIdx.x;
    int stride = gridDim.x * blockDim.x;
    for (int j = i; j < BSZ * DIMV; j += stride) g_hT[j] = 0.f;
    // zero pad columns [200,208) of gAh
    if (i < BSZ * 8) gAh[(i >> 3) * KDPAD + DIMV + (i & 7)] = __float2half(0.f);
    if (i < 8) g_acc[i] = 0.f;
    if (i == 0) {
        int odd = xraw[1] | xraw[3] | xraw[5] | xraw[7] |
                  xraw[9] | xraw[11] | xraw[13] | xraw[15];
        g_idx64 = (odd == 0) ? 1 : 0;
    }
}

// ---------------- E -> fp16, padded ----------------
__global__ void k_ehalf(const float* __restrict__ E) {
    long idx = (long)blockIdx.x * blockDim.x + threadIdx.x;
    if (idx >= (long)NEPAD * 26) return;
    int row = (int)(idx / 26);
    int c8  = (int)(idx % 26) * 8;
    long o  = (long)row * KDPAD + c8;
    if (row < NENT && c8 < DIMV) {
        const float* p = E + (long)row * DIMV + c8;
        #pragma unroll
        for (int j = 0; j < 8; j++) gEh[o + j] = __float2half(p[j]);
    } else {
        #pragma unroll
        for (int j = 0; j < 8; j++) gEh[o + j] = __float2half(0.f);
    }
}

// ---------------- transpose W -> gWTh[e][K] fp16 (256 rows zero-padded), fused norm4(W) ----------------
__global__ void k_whalf(const float* __restrict__ W) {
    __shared__ float sT[32][33];
    __shared__ float sr[8];
    int K0 = blockIdx.x * 32;   // 1250
    int e0 = blockIdx.y * 32;   // 8 -> 256 rows
    int tx = threadIdx.x & 31, ty = threadIdx.x >> 5;
    float p4 = 0.f;
    #pragma unroll
    for (int r = 0; r < 4; r++) {
        int Kr = K0 + ty + 8 * r;
        int e  = e0 + tx;
        float v = (e < DIMV) ? W[(long)Kr * DIMV + e] : 0.f;
        sT[ty + 8 * r][tx] = v;
        float a = v * v; p4 += a * a;
    }
    __syncthreads();
    #pragma unroll
    for (int r = 0; r < 4; r++) {
        int ew = e0 + ty + 8 * r;
        if (ew < KWROWS)
            gWTh[(long)ew * KBIG + K0 + tx] = __float2half(sT[tx][ty + 8 * r]);
    }
    #pragma unroll
    for (int o = 16; o > 0; o >>= 1) p4 += __shfl_down_sync(0xffffffffu, p4, o);
    if (tx == 0) sr[ty] = p4;
    __syncthreads();
    if (threadIdx.x == 0) {
        float s = 0.f;
        for (int i = 0; i < 8; i++) s += sr[i];
        atomicAdd(&g_acc[4], s);
    }
}

// ---------------- K1: gather (transposed writes) + reg norms 1..3 ----------------
__global__ void k_gather(const int* __restrict__ x32,
                         const float* __restrict__ E,
                         const float* __restrict__ R,
                         const float* __restrict__ RnoT,
                         const float* __restrict__ T) {
    __shared__ int sidx[4];
    __shared__ float sr[3][8];
    int b = blockIdx.x, t = threadIdx.x;
    if (t < 4) {
        int v;
        if (g_idx64) { const long long* x64 = (const long long*)x32; v = (int)x64[(long)b * 4 + t]; }
        else         { v = x32[b * 4 + t]; }
        sidx[t] = v;
    }
    __syncthreads();
    int x0 = sidx[0], x1 = sidx[1], x2 = sidx[2], x3 = sidx[3];
    float p1 = 0.f, p2 = 0.f, p3 = 0.f;
    if (t < DIMV) {
        float lv = E[(long)x0 * DIMV + t];
        float rv = R[x1 * DIMV + t];
        float tv = T[x3 * DIMV + t];
        float rt = rv * tv;
        g_lhsT[t * BSZ + b]  = lv;
        g_reltT[t * BSZ + b] = rt;
        float rn = RnoT[x1 * DIMV + t];
        float rh = E[(long)x2 * DIMV + t];
        float a = rt * rt;  p1 = a * a;
        float c = rn * rn;  p2 = c * c;
        float e2 = rh * rh; p3 = e2 * e2;
    }
    #pragma unroll
    for (int o = 16; o > 0; o >>= 1) {
        p1 += __shfl_down_sync(0xffffffffu, p1, o);
        p2 += __shfl_down_sync(0xffffffffu, p2, o);
        p3 += __shfl_down_sync(0xffffffffu, p3, o);
    }
    int lane = t & 31, w = t >> 5;
    if (lane == 0) { sr[0][w] = p1; sr[1][w] = p2; sr[2][w] = p3; }
    __syncthreads();
    if (t == 0) {
        float s1 = 0.f, s2 = 0.f, s3 = 0.f;
        for (int i = 0; i < 8; i++) { s1 += sr[0][i]; s2 += sr[1][i]; s3 += sr[2][i]; }
        atomicAdd(&g_acc[1], s1);
        atomicAdd(&g_acc[2], s2);
        atomicAdd(&g_acc[3], s3);
    }
}

// ---------------- K2: fused BN0 (stats + normalize) + norm4(lhs_n); one block per feature ----------------
__global__ __launch_bounds__(256) void k_bn0(const float* __restrict__ gamma,
                                             const float* __restrict__ beta) {
    __shared__ float s1[8], s2[8], sSS[2];
    int d = blockIdx.x, t = threadIdx.x;
    float4 v0 = *(const float4*)&g_lhsT[d * BSZ + t * 8];
    float4 v1 = *(const float4*)&g_lhsT[d * BSZ + t * 8 + 4];
    float vs[8] = {v0.x, v0.y, v0.z, v0.w, v1.x, v1.y, v1.z, v1.w};
    float sum = 0.f, sq = 0.f;
    #pragma unroll
    for (int j = 0; j < 8; j++) { sum += vs[j]; sq += vs[j] * vs[j]; }
    #pragma unroll
    for (int o = 16; o > 0; o >>= 1) {
        sum += __shfl_down_sync(0xffffffffu, sum, o);
        sq  += __shfl_down_sync(0xffffffffu, sq, o);
    }
    int lane = t & 31, w = t >> 5;
    if (lane == 0) { s1[w] = sum; s2[w] = sq; }
    __syncthreads();
    if (t == 0) {
        float S = 0.f, Q = 0.f;
        for (int i = 0; i < 8; i++) { S += s1[i]; Q += s2[i]; }
        float mean = S * (1.f / BSZ);
        float var  = Q * (1.f / BSZ) - mean * mean;
        float inv  = rsqrtf(var + EPSV);
        float sc   = gamma[d] * inv;
        sSS[0] = sc;
        sSS[1] = beta[d] - mean * sc;
    }
    __syncthreads();
    float sc = sSS[0], sh = sSS[1];
    float p4 = 0.f;
    #pragma unroll
    for (int j = 0; j < 8; j++) {
        float nv = vs[j] * sc + sh;
        vs[j] = nv;
        float a = nv * nv; p4 += a * a;
    }
    *(float4*)&g_lhsnT[d * BSZ + t * 8]     = make_float4(vs[0], vs[1], vs[2], vs[3]);
    *(float4*)&g_lhsnT[d * BSZ + t * 8 + 4] = make_float4(vs[4], vs[5], vs[6], vs[7]);
    #pragma unroll
    for (int o = 16; o > 0; o >>= 1) p4 += __shfl_down_sync(0xffffffffu, p4, o);
    if (lane == 0) s1[w] = p4;
    __syncthreads();
    if (t == 0) {
        float s = 0.f;
        for (int i = 0; i < 8; i++) s += s1[i];
        atomicAdd(&g_acc[0], s);
    }
}

// ---------------- K4: h GEMM, fp16 MMA single-pass ----------------
// C(2048x200) = A(2048x40000) * WT^T ; tile M=128(b) x N=64(e), K-split z=10.
__global__ __launch_bounds__(256) void k_hgemm() {
    __shared__ __align__(16) __half sAh[2][128 * KP];
    __shared__ __align__(16) __half sWh[2][64 * KP];
    const int t    = threadIdx.x;
    const int lane = t & 31;
    const int w    = t >> 5;
    const int wm   = (w & 1) * 64;
    const int wn   = (w >> 1) * 16;
    const int b0   = blockIdx.x * 128;
    const int e0   = blockIdx.y * 64;
    const int cbeg = blockIdx.z * 250;

    const uint32_t uAh = (uint32_t)__cvta_generic_to_shared(sAh);
    const uint32_t uWh = (uint32_t)__cvta_generic_to_shared(sWh);
    const uint32_t bufA = 128 * KP * 2;
    const uint32_t bufW = 64 * KP * 2;

    const int kk = t & 15;
    const int m4 = t >> 4;

    auto stageW = [&](int buf, int kc) {
        if (t < 128) {
            const __half* src = gWTh + (long)(e0 + (t >> 1)) * KBIG + kc + (t & 1) * 8;
            uint32_t dst = uWh + buf * bufW + (uint32_t)(((t >> 1)) * KP + (t & 1) * 8) * 2;
            CPA16(dst, src);
        }
    };
    auto stageA = [&](int buf, int kc) {
        int K = kc + kk;
        int k = K / DIMV;
        int d = K - k * DIMV;
        const float* rp = &g_reltT[k * BSZ + b0 + m4 * 8];
        const float* lp = &g_lhsnT[d * BSZ + b0 + m4 * 8];
        #pragma unroll
        for (int g = 0; g < 2; g++) {
            float4 rv = *(const float4*)(rp + g * 4);
            float4 lv = *(const float4*)(lp + g * 4);
            float pr[4] = {rv.x * lv.x, rv.y * lv.y, rv.z * lv.z, rv.w * lv.w};
            #pragma unroll
            for (int j = 0; j < 4; j++)
                sAh[buf][(m4 * 8 + g * 4 + j) * KP + kk] = __float2half(pr[j]);
        }
    };

    float c[4][2][4];
    #pragma unroll
    for (int mi = 0; mi < 4; mi++)
        #pragma unroll
        for (int ni = 0; ni < 2; ni++)
            #pragma unroll
            for (int q = 0; q < 4; q++) c[mi][ni][q] = 0.f;

    stageW(0, cbeg * 16);
    CP_COMMIT();
    stageA(0, cbeg * 16);

    for (int cI = 0; cI < 250; cI++) {
        int buf = cI & 1;
        if (cI + 1 < 250) {
            stageW(buf ^ 1, (cbeg + cI + 1) * 16);
            CP_COMMIT();
            stageA(buf ^ 1, (cbeg + cI + 1) * 16);
        } else {
            CP_COMMIT();
        }
        CP_WAIT1();
        __syncthreads();

        uint32_t aAh = uAh + buf * bufA;
        uint32_t aWh = uWh + buf * bufW;
        uint32_t ah[4][4];
        {
            int arow = wm + (lane & 15);
            int acol = (lane >> 4) * 8;
            #pragma unroll
            for (int mi = 0; mi < 4; mi++) {
                uint32_t off = (uint32_t)(((arow + mi * 16) * KP + acol) * 2);
                ldsm_x4(ah[mi][0], ah[mi][1], ah[mi][2], ah[mi][3], aAh + off);
            }
        }
        uint32_t bh[4];
        {
            int r = lane & 7, seg = lane >> 3;
            int brow = wn + ((seg & 2) ? 8 : 0) + r;
            int bcol = (seg & 1) * 8;
            uint32_t off = (uint32_t)((brow * KP + bcol) * 2);
            ldsm_x4(bh[0], bh[1], bh[2], bh[3], aWh + off);
        }
        #pragma unroll
        for (int mi = 0; mi < 4; mi++) {
            #pragma unroll
            for (int ni = 0; ni < 2; ni++) {
                float* cc = c[mi][ni];
                mma_f16(cc[0], cc[1], cc[2], cc[3],
                        ah[mi][0], ah[mi][1], ah[mi][2], ah[mi][3], bh[ni * 2], bh[ni * 2 + 1]);
            }
        }
        __syncthreads();
    }

    #pragma unroll
    for (int mi = 0; mi < 4; mi++) {
        #pragma unroll
        for (int ni = 0; ni < 2; ni++) {
            int r  = b0 + wm + mi * 16 + (lane >> 2);
            int cg = e0 + wn + ni * 8 + (lane & 3) * 2;
            if (cg < DIMV) {
                float* cc = c[mi][ni];
                atomicAdd(&g_hT[cg * BSZ + r], cc[0]);
                atomicAdd(&g_hT[(cg + 1) * BSZ + r], cc[1]);
                atomicAdd(&g_hT[cg * BSZ + r + 8], cc[2]);
                atomicAdd(&g_hT[(cg + 1) * BSZ + r + 8], cc[3]);
            }
        }
    }
}

// ---------------- K5: fused BN1 -> gAh fp16 [b][K] ----------------
__global__ __launch_bounds__(256) void k_bn1(const float* __restrict__ gamma,
                                             const float* __restrict__ beta) {
    __shared__ float s1[8], s2[8], sSS[2];
    int e = blockIdx.x, t = threadIdx.x;
    float4 v0 = *(const float4*)&g_hT[e * BSZ + t * 8];
    float4 v1 = *(const float4*)&g_hT[e * BSZ + t * 8 + 4];
    float vs[8] = {v0.x, v0.y, v0.z, v0.w, v1.x, v1.y, v1.z, v1.w};
    float sum = 0.f, sq = 0.f;
    #pragma unroll
    for (int j = 0; j < 8; j++) { sum += vs[j]; sq += vs[j] * vs[j]; }
    #pragma unroll
    for (int o = 16; o > 0; o >>= 1) {
        sum += __shfl_down_sync(0xffffffffu, sum, o);
        sq  += __shfl_down_sync(0xffffffffu, sq, o);
    }
    int lane = t & 31, w = t >> 5;
    if (lane == 0) { s1[w] = sum; s2[w] = sq; }
    __syncthreads();
    if (t == 0) {
        float S = 0.f, Q = 0.f;
        for (int i = 0; i < 8; i++) { S += s1[i]; Q += s2[i]; }
        float mean = S * (1.f / BSZ);
        float var  = Q * (1.f / BSZ) - mean * mean;
        float inv  = rsqrtf(var + EPSV);
        float sc   = gamma[e] * inv;
        sSS[0] = sc;
        sSS[1] = beta[e] - mean * sc;
    }
    __syncthreads();
    float sc = sSS[0], sh = sSS[1];
    #pragma unroll
    for (int j = 0; j < 8; j++)
        gAh[(t * 8 + j) * KDPAD + e] = __float2half(vs[j] * sc + sh);
}

// ---------------- K7: pred = h_n @ E^T, fp16 MMA single-pass ----------------
__global__ __launch_bounds__(256) void k_pred(float* __restrict__ out) {
    __shared__ __align__(16) __half sAh[2][128 * KP];
    __shared__ __align__(16) __half sBh[2][128 * KP];
    const int t    = threadIdx.x;
    const int lane = t & 31;
    const int w    = t >> 5;
    const int wm   = (w & 1) * 64;
    const int wn   = (w >> 1) * 32;
    const int b0   = blockIdx.x * 128;
    const int e0   = blockIdx.y * 128;

    const uint32_t uAh = (uint32_t)__cvta_generic_to_shared(sAh);
    const uint32_t uBh = (uint32_t)__cvta_generic_to_shared(sBh);
    const uint32_t bufSz = 128 * KP * 2;

    const int srow = t >> 1;
    const int sch  = (t & 1) * 8;
    auto stage = [&](int buf, int kc) {
        uint32_t doff = buf * bufSz + (uint32_t)(srow * KP + sch) * 2;
        CPA16(uAh + doff, gAh + (long)(b0 + srow) * KDPAD + kc + sch);
        CPA16(uBh + doff, gEh + (long)(e0 + srow) * KDPAD + kc + sch);
    };

    float c[4][4][4];
    #pragma unroll
    for (int mi = 0; mi < 4; mi++)
        #pragma unroll
        for (int ni = 0; ni < 4; ni++)
            #pragma unroll
            for (int q = 0; q < 4; q++) c[mi][ni][q] = 0.f;

    stage(0, 0);
    CP_COMMIT();

    for (int cI = 0; cI < 13; cI++) {
        int buf = cI & 1;
        if (cI + 1 < 13) stage(buf ^ 1, (cI + 1) * 16);
        CP_COMMIT();
        CP_WAIT1();
        __syncthreads();

        uint32_t aAh = uAh + buf * bufSz;
        uint32_t aBh = uBh + buf * bufSz;
        uint32_t ah[4][4];
        {
            int arow = wm + (lane & 15);
            int acol = (lane >> 4) * 8;
            #pragma unroll
            for (int mi = 0; mi < 4; mi++) {
                uint32_t off = (uint32_t)(((arow + mi * 16) * KP + acol) * 2);
                ldsm_x4(ah[mi][0], ah[mi][1], ah[mi][2], ah[mi][3], aAh + off);
            }
        }
        uint32_t bh[2][4];
        {
            int r = lane & 7, seg = lane >> 3;
            int brow_in = ((seg & 2) ? 8 : 0) + r;
            int bcol = (seg & 1) * 8;
            #pragma unroll
            for (int p = 0; p < 2; p++) {
                uint32_t off = (uint32_t)(((wn + p * 16 + brow_in) * KP + bcol) * 2);
                ldsm_x4(bh[p][0], bh[p][1], bh[p][2], bh[p][3], aBh + off);
            }
        }
        #pragma unroll
        for (int mi = 0; mi < 4; mi++) {
            #pragma unroll
            for (int ni = 0; ni < 4; ni++) {
                int p = ni >> 1, q = (ni & 1) * 2;
                float* cc = c[mi][ni];
                mma_f16(cc[0], cc[1], cc[2], cc[3],
                        ah[mi][0], ah[mi][1], ah[mi][2], ah[mi][3], bh[p][q], bh[p][q + 1]);
            }
        }
        __syncthreads();
    }

    #pragma unroll
    for (int mi = 0; mi < 4; mi++) {
        #pragma unroll
        for (int ni = 0; ni < 4; ni++) {
            int r  = b0 + wm + mi * 16 + (lane >> 2);
            int cg = e0 + wn + ni * 8 + (lane & 3) * 2;
            if (cg < NENT) {
                float* cc = c[mi][ni];
                *(float2*)&out[(long)r * NENT + cg]       = make_float2(cc[0], cc[1]);
                *(float2*)&out[(long)(r + 8) * NENT + cg] = make_float2(cc[2], cc[3]);
            }
        }
    }
}

// ---------------- K9: reg outputs + T passthrough ----------------
__global__ void k_tail(const float* __restrict__ T, float* __restrict__ out) {
    int i = blockIdx.x * blockDim.x + threadIdx.x;
    if (i < 5) out[REG_OFF + i] = powf(g_acc[i], 0.25f);
    if (i < NTS * DIMV) out[T_OFF + i] = T[i];
}

// ---------------- launch ----------------
extern "C" void kernel_launch(void* const* d_in, const int* in_sizes, int n_in,
                              void* d_out, int out_size) {
    const int*   x    = (const int*)d_in[0];
    const float* E    = (const float*)d_in[1];
    const float* R    = (const float*)d_in[2];
    const float* RnoT = (const float*)d_in[3];
    const float* T    = (const float*)d_in[4];
    const float* W    = (const float*)d_in[5];
    const float* g0   = (const float*)d_in[6];
    const float* be0  = (const float*)d_in[7];
    const float* g1   = (const float*)d_in[8];
    const float* be1  = (const float*)d_in[9];
    float* out = (float*)d_out;

    k_init<<<512, 256>>>(x);
    k_ehalf<<<(int)(((long)NEPAD * 26 + 255) / 256), 256>>>(E);
    k_whalf<<<dim3(1250, 8), 256>>>(W);
    k_gather<<<BSZ, 256>>>(x, E, R, RnoT, T);
    k_bn0<<<DIMV, 256>>>(g0, be0);
    k_hgemm<<<dim3(16, 4, 10), 256>>>();
    k_bn1<<<DIMV, 256>>>(g1, be1);
    k_pred<<<dim3(16, 782), 256>>>(out);
    k_tail<<<320, 256>>>(T, out);
}

// round 7
// speedup vs baseline: 2.9713x; 1.0265x over previous
#include <cuda_runtime.h>
#include <cuda_fp16.h>
#include <math.h>
#include <stdint.h>

#define BSZ   2048
#define DIMV  200
#define NENT  100000
#define NTS   400
#define EPSV  1e-5f
#define REG_OFF 204800000L
#define T_OFF   204800005L
#define KP    24            // A smem row pitch in halves (48B)
#define EP    216           // E smem row pitch in halves (432B)
#define NEPAD 100096        // 782*128
#define KDPAD 208           // DIMV padded to mult of 16 (K of pred GEMM)
#define KWROWS 256          // W-transpose rows padded to N-tile coverage (4 x 64)
#define KBIG  40000         // inner K of hgemm
#define PRED_SMEM (128*EP*2 + 2*128*KP*2)   // 55296 + 12288 = 67584 bytes

// ---------------- device-global scratch ----------------
__device__ __align__(16) float g_lhsT[DIMV * BSZ];    // lhs transposed [d][b]
__device__ __align__(16) float g_reltT[DIMV * BSZ];   // rel*time [k][b]
__device__ __align__(16) float g_lhsnT[DIMV * BSZ];   // bn0(lhs) [d][b]
__device__ __align__(16) float g_hT[DIMV * BSZ];      // h transposed [e][b]
__device__ float g_acc[8];
__device__ int   g_idx64;
// fp16 operands
__device__ __align__(16) __half gEh[(long)NEPAD * KDPAD];
__device__ __align__(16) __half gWTh[(long)KWROWS * KBIG]; // [e][K]
__device__ __align__(16) __half gAh[BSZ * KDPAD];          // h_n fp16 [b][K]

// ---------------- helpers ----------------
__device__ __forceinline__ void ldsm_x4(uint32_t& r0, uint32_t& r1, uint32_t& r2, uint32_t& r3,
                                        uint32_t addr) {
    asm volatile("ldmatrix.sync.aligned.m8n8.x4.shared.b16 {%0,%1,%2,%3}, [%4];"
                 : "=r"(r0), "=r"(r1), "=r"(r2), "=r"(r3) : "r"(addr));
}
__device__ __forceinline__ void mma_f16(float& c0, float& c1, float& c2, float& c3,
                                        uint32_t a0, uint32_t a1, uint32_t a2, uint32_t a3,
                                        uint32_t b0, uint32_t b1) {
    asm volatile("mma.sync.aligned.m16n8k16.row.col.f32.f16.f16.f32 "
                 "{%0,%1,%2,%3},{%4,%5,%6,%7},{%8,%9},{%0,%1,%2,%3};"
                 : "+f"(c0), "+f"(c1), "+f"(c2), "+f"(c3)
                 : "r"(a0), "r"(a1), "r"(a2), "r"(a3), "r"(b0), "r"(b1));
}
#define CPA16(dst_u32, src_ptr) \
    asm volatile("cp.async.cg.shared.global [%0], [%1], 16;" :: "r"(dst_u32), "l"(src_ptr))
#define CP_COMMIT() asm volatile("cp.async.commit_group;")
#define CP_WAIT1()  asm volatile("cp.async.wait_group 1;")
#define CP_WAIT0()  asm volatile("cp.async.wait_group 0;")

// ---------------- K0: zero + pad + index width ----------------
__global__ void k_init(const int* __restrict__ xraw) {
    int i = blockIdx.x * blockDim.x + threadIdx.x;
    int stride = gridDim.x * blockDim.x;
    for (int j = i; j < BSZ * DIMV; j += stride) g_hT[j] = 0.f;
    if (i < BSZ * 8) gAh[(i >> 3) * KDPAD + DIMV + (i & 7)] = __float2half(0.f);
    if (i < 8) g_acc[i] = 0.f;
    if (i == 0) {
        int odd = xraw[1] | xraw[3] | xraw[5] | xraw[7] |
                  xraw[9] | xraw[11] | xraw[13] | xraw[15];
        g_idx64 = (odd == 0) ? 1 : 0;
    }
}

// ---------------- E -> fp16, padded ----------------
__global__ void k_ehalf(const float* __restrict__ E) {
    long idx = (long)blockIdx.x * blockDim.x + threadIdx.x;
    if (idx >= (long)NEPAD * 26) return;
    int row = (int)(idx / 26);
    int c8  = (int)(idx % 26) * 8;
    long o  = (long)row * KDPAD + c8;
    if (row < NENT && c8 < DIMV) {
        const float* p = E + (long)row * DIMV + c8;
        #pragma unroll
        for (int j = 0; j < 8; j++) gEh[o + j] = __float2half(p[j]);
    } else {
        #pragma unroll
        for (int j = 0; j < 8; j++) gEh[o + j] = __float2half(0.f);
    }
}

// ---------------- transpose W -> gWTh[e][K] fp16 (zero-padded), fused norm4(W) ----------------
__global__ void k_whalf(const float* __restrict__ W) {
    __shared__ float sT[32][33];
    __shared__ float sr[8];
    int K0 = blockIdx.x * 32;
    int e0 = blockIdx.y * 32;
    int tx = threadIdx.x & 31, ty = threadIdx.x >> 5;
    float p4 = 0.f;
    #pragma unroll
    for (int r = 0; r < 4; r++) {
        int Kr = K0 + ty + 8 * r;
        int e  = e0 + tx;
        float v = (e < DIMV) ? W[(long)Kr * DIMV + e] : 0.f;
        sT[ty + 8 * r][tx] = v;
        float a = v * v; p4 += a * a;
    }
    __syncthreads();
    #pragma unroll
    for (int r = 0; r < 4; r++) {
        int ew = e0 + ty + 8 * r;
        if (ew < KWROWS)
            gWTh[(long)ew * KBIG + K0 + tx] = __float2half(sT[tx][ty + 8 * r]);
    }
    #pragma unroll
    for (int o = 16; o > 0; o >>= 1) p4 += __shfl_down_sync(0xffffffffu, p4, o);
    if (tx == 0) sr[ty] = p4;
    __syncthreads();
    if (threadIdx.x == 0) {
        float s = 0.f;
        for (int i = 0; i < 8; i++) s += sr[i];
        atomicAdd(&g_acc[4], s);
    }
}

// ---------------- K1: gather (transposed writes) + reg norms 1..3 ----------------
__global__ void k_gather(const int* __restrict__ x32,
                         const float* __restrict__ E,
                         const float* __restrict__ R,
                         const float* __restrict__ RnoT,
                         const float* __restrict__ T) {
    __shared__ int sidx[4];
    __shared__ float sr[3][8];
    int b = blockIdx.x, t = threadIdx.x;
    if (t < 4) {
        int v;
        if (g_idx64) { const long long* x64 = (const long long*)x32; v = (int)x64[(long)b * 4 + t]; }
        else         { v = x32[b * 4 + t]; }
        sidx[t] = v;
    }
    __syncthreads();
    int x0 = sidx[0], x1 = sidx[1], x2 = sidx[2], x3 = sidx[3];
    float p1 = 0.f, p2 = 0.f, p3 = 0.f;
    if (t < DIMV) {
        float lv = E[(long)x0 * DIMV + t];
        float rv = R[x1 * DIMV + t];
        float tv = T[x3 * DIMV + t];
        float rt = rv * tv;
        g_lhsT[t * BSZ + b]  = lv;
        g_reltT[t * BSZ + b] = rt;
        float rn = RnoT[x1 * DIMV + t];
        float rh = E[(long)x2 * DIMV + t];
        float a = rt * rt;  p1 = a * a;
        float c = rn * rn;  p2 = c * c;
        float e2 = rh * rh; p3 = e2 * e2;
    }
    #pragma unroll
    for (int o = 16; o > 0; o >>= 1) {
        p1 += __shfl_down_sync(0xffffffffu, p1, o);
        p2 += __shfl_down_sync(0xffffffffu, p2, o);
        p3 += __shfl_down_sync(0xffffffffu, p3, o);
    }
    int lane = t & 31, w = t >> 5;
    if (lane == 0) { sr[0][w] = p1; sr[1][w] = p2; sr[2][w] = p3; }
    __syncthreads();
    if (t == 0) {
        float s1 = 0.f, s2 = 0.f, s3 = 0.f;
        for (int i = 0; i < 8; i++) { s1 += sr[0][i]; s2 += sr[1][i]; s3 += sr[2][i]; }
        atomicAdd(&g_acc[1], s1);
        atomicAdd(&g_acc[2], s2);
        atomicAdd(&g_acc[3], s3);
    }
}

// ---------------- K2: fused BN0 + norm4(lhs_n); one block per feature ----------------
__global__ __launch_bounds__(256) void k_bn0(const float* __restrict__ gamma,
                                             const float* __restrict__ beta) {
    __shared__ float s1[8], s2[8], sSS[2];
    int d = blockIdx.x, t = threadIdx.x;
    float4 v0 = *(const float4*)&g_lhsT[d * BSZ + t * 8];
    float4 v1 = *(const float4*)&g_lhsT[d * BSZ + t * 8 + 4];
    float vs[8] = {v0.x, v0.y, v0.z, v0.w, v1.x, v1.y, v1.z, v1.w};
    float sum = 0.f, sq = 0.f;
    #pragma unroll
    for (int j = 0; j < 8; j++) { sum += vs[j]; sq += vs[j] * vs[j]; }
    #pragma unroll
    for (int o = 16; o > 0; o >>= 1) {
        sum += __shfl_down_sync(0xffffffffu, sum, o);
        sq  += __shfl_down_sync(0xffffffffu, sq, o);
    }
    int lane = t & 31, w = t >> 5;
    if (lane == 0) { s1[w] = sum; s2[w] = sq; }
    __syncthreads();
    if (t == 0) {
        float S = 0.f, Q = 0.f;
        for (int i = 0; i < 8; i++) { S += s1[i]; Q += s2[i]; }
        float mean = S * (1.f / BSZ);
        float var  = Q * (1.f / BSZ) - mean * mean;
        float inv  = rsqrtf(var + EPSV);
        float sc   = gamma[d] * inv;
        sSS[0] = sc;
        sSS[1] = beta[d] - mean * sc;
    }
    __syncthreads();
    float sc = sSS[0], sh = sSS[1];
    float p4 = 0.f;
    #pragma unroll
    for (int j = 0; j < 8; j++) {
        float nv = vs[j] * sc + sh;
        vs[j] = nv;
        float a = nv * nv; p4 += a * a;
    }
    *(float4*)&g_lhsnT[d * BSZ + t * 8]     = make_float4(vs[0], vs[1], vs[2], vs[3]);
    *(float4*)&g_lhsnT[d * BSZ + t * 8 + 4] = make_float4(vs[4], vs[5], vs[6], vs[7]);
    #pragma unroll
    for (int o = 16; o > 0; o >>= 1) p4 += __shfl_down_sync(0xffffffffu, p4, o);
    if (lane == 0) s1[w] = p4;
    __syncthreads();
    if (t == 0) {
        float s = 0.f;
        for (int i = 0; i < 8; i++) s += s1[i];
        atomicAdd(&g_acc[0], s);
    }
}

// ---------------- K4: h GEMM, fp16 MMA single-pass ----------------
__global__ __launch_bounds__(256) void k_hgemm() {
    __shared__ __align__(16) __half sAh[2][128 * KP];
    __shared__ __align__(16) __half sWh[2][64 * KP];
    const int t    = threadIdx.x;
    const int lane = t & 31;
    const int w    = t >> 5;
    const int wm   = (w & 1) * 64;
    const int wn   = (w >> 1) * 16;
    const int b0   = blockIdx.x * 128;
    const int e0   = blockIdx.y * 64;
    const int cbeg = blockIdx.z * 250;

    const uint32_t uAh = (uint32_t)__cvta_generic_to_shared(sAh);
    const uint32_t uWh = (uint32_t)__cvta_generic_to_shared(sWh);
    const uint32_t bufA = 128 * KP * 2;
    const uint32_t bufW = 64 * KP * 2;

    const int kk = t & 15;
    const int m4 = t >> 4;

    auto stageW = [&](int buf, int kc) {
        if (t < 128) {
            const __half* src = gWTh + (long)(e0 + (t >> 1)) * KBIG + kc + (t & 1) * 8;
            uint32_t dst = uWh + buf * bufW + (uint32_t)(((t >> 1)) * KP + (t & 1) * 8) * 2;
            CPA16(dst, src);
        }
    };
    auto stageA = [&](int buf, int kc) {
        int K = kc + kk;
        int k = K / DIMV;
        int d = K - k * DIMV;
        const float* rp = &g_reltT[k * BSZ + b0 + m4 * 8];
        const float* lp = &g_lhsnT[d * BSZ + b0 + m4 * 8];
        #pragma unroll
        for (int g = 0; g < 2; g++) {
            float4 rv = *(const float4*)(rp + g * 4);
            float4 lv = *(const float4*)(lp + g * 4);
            float pr[4] = {rv.x * lv.x, rv.y * lv.y, rv.z * lv.z, rv.w * lv.w};
            #pragma unroll
            for (int j = 0; j < 4; j++)
                sAh[buf][(m4 * 8 + g * 4 + j) * KP + kk] = __float2half(pr[j]);
        }
    };

    float c[4][2][4];
    #pragma unroll
    for (int mi = 0; mi < 4; mi++)
        #pragma unroll
        for (int ni = 0; ni < 2; ni++)
            #pragma unroll
            for (int q = 0; q < 4; q++) c[mi][ni][q] = 0.f;

    stageW(0, cbeg * 16);
    CP_COMMIT();
    stageA(0, cbeg * 16);

    for (int cI = 0; cI < 250; cI++) {
        int buf = cI & 1;
        if (cI + 1 < 250) {
            stageW(buf ^ 1, (cbeg + cI + 1) * 16);
            CP_COMMIT();
            stageA(buf ^ 1, (cbeg + cI + 1) * 16);
        } else {
            CP_COMMIT();
        }
        CP_WAIT1();
        __syncthreads();

        uint32_t aAh = uAh + buf * bufA;
        uint32_t aWh = uWh + buf * bufW;
        uint32_t ah[4][4];
        {
            int arow = wm + (lane & 15);
            int acol = (lane >> 4) * 8;
            #pragma unroll
            for (int mi = 0; mi < 4; mi++) {
                uint32_t off = (uint32_t)(((arow + mi * 16) * KP + acol) * 2);
                ldsm_x4(ah[mi][0], ah[mi][1], ah[mi][2], ah[mi][3], aAh + off);
            }
        }
        uint32_t bh[4];
        {
            int r = lane & 7, seg = lane >> 3;
            int brow = wn + ((seg & 2) ? 8 : 0) + r;
            int bcol = (seg & 1) * 8;
            uint32_t off = (uint32_t)((brow * KP + bcol) * 2);
            ldsm_x4(bh[0], bh[1], bh[2], bh[3], aWh + off);
        }
        #pragma unroll
        for (int mi = 0; mi < 4; mi++) {
            #pragma unroll
            for (int ni = 0; ni < 2; ni++) {
                float* cc = c[mi][ni];
                mma_f16(cc[0], cc[1], cc[2], cc[3],
                        ah[mi][0], ah[mi][1], ah[mi][2], ah[mi][3], bh[ni * 2], bh[ni * 2 + 1]);
            }
        }
        __syncthreads();
    }

    #pragma unroll
    for (int mi = 0; mi < 4; mi++) {
        #pragma unroll
        for (int ni = 0; ni < 2; ni++) {
            int r  = b0 + wm + mi * 16 + (lane >> 2);
            int cg = e0 + wn + ni * 8 + (lane & 3) * 2;
            if (cg < DIMV) {
                float* cc = c[mi][ni];
                atomicAdd(&g_hT[cg * BSZ + r], cc[0]);
                atomicAdd(&g_hT[(cg + 1) * BSZ + r], cc[1]);
                atomicAdd(&g_hT[cg * BSZ + r + 8], cc[2]);
                atomicAdd(&g_hT[(cg + 1) * BSZ + r + 8], cc[3]);
            }
        }
    }
}

// ---------------- K5: fused BN1 -> gAh fp16 [b][K] ----------------
__global__ __launch_bounds__(256) void k_bn1(const float* __restrict__ gamma,
                                             const float* __restrict__ beta) {
    __shared__ float s1[8], s2[8], sSS[2];
    int e = blockIdx.x, t = threadIdx.x;
    float4 v0 = *(const float4*)&g_hT[e * BSZ + t * 8];
    float4 v1 = *(const float4*)&g_hT[e * BSZ + t * 8 + 4];
    float vs[8] = {v0.x, v0.y, v0.z, v0.w, v1.x, v1.y, v1.z, v1.w};
    float sum = 0.f, sq = 0.f;
    #pragma unroll
    for (int j = 0; j < 8; j++) { sum += vs[j]; sq += vs[j] * vs[j]; }
    #pragma unroll
    for (int o = 16; o > 0; o >>= 1) {
        sum += __shfl_down_sync(0xffffffffu, sum, o);
        sq  += __shfl_down_sync(0xffffffffu, sq, o);
    }
    int lane = t & 31, w = t >> 5;
    if (lane == 0) { s1[w] = sum; s2[w] = sq; }
    __syncthreads();
    if (t == 0) {
        float S = 0.f, Q = 0.f;
        for (int i = 0; i < 8; i++) { S += s1[i]; Q += s2[i]; }
        float mean = S * (1.f / BSZ);
        float var  = Q * (1.f / BSZ) - mean * mean;
        float inv  = rsqrtf(var + EPSV);
        float sc   = gamma[e] * inv;
        sSS[0] = sc;
        sSS[1] = beta[e] - mean * sc;
    }
    __syncthreads();
    float sc = sSS[0], sh = sSS[1];
    #pragma unroll
    for (int j = 0; j < 8; j++)
        gAh[(t * 8 + j) * KDPAD + e] = __float2half(vs[j] * sc + sh);
}

// ---------------- K7: pred = h_n @ E^T, E-stationary persistent-M ----------------
// One CTA per 128-col e-tile. E tile staged ONCE into smem (128 rows x 26 16B
// chunks = full 416B rows); loop over 16 m-tiles with double-buffered A chunks.
__global__ __launch_bounds__(256) void k_pred(float* __restrict__ out) {
    extern __shared__ __align__(16) char dynsmem[];
    __half* sE = (__half*)dynsmem;                       // 128 x EP
    __half* sA = (__half*)(dynsmem + 128 * EP * 2);      // 2 x 128 x KP
    const int t    = threadIdx.x;
    const int lane = t & 31;
    const int w    = t >> 5;
    const int wm   = (w & 1) * 64;
    const int wn   = (w >> 1) * 32;
    const int e0   = blockIdx.x * 128;

    const uint32_t uE = (uint32_t)__cvta_generic_to_shared(sE);
    const uint32_t uA = (uint32_t)__cvta_generic_to_shared(sA);
    const uint32_t bufA = 128 * KP * 2;

    // ---- stage E tile once: 128 rows x 26 16B-chunks (full 208-half rows) ----
    for (int i = t; i < 128 * 26; i += 256) {
        int row = i / 26, c = i - row * 26;
        CPA16(uE + (uint32_t)(row * EP + c * 8) * 2,
              gEh + (long)(e0 + row) * KDPAD + c * 8);
    }
    CP_COMMIT();

    const int srow = t >> 1;
    const int sch  = (t & 1) * 8;
    auto stageA = [&](int buf, int mIdx, int kcIdx) {
        CPA16(uA + buf * bufA + (uint32_t)(srow * KP + sch) * 2,
              gAh + (long)(mIdx * 128 + srow) * KDPAD + kcIdx * 16 + sch);
    };

    stageA(0, 0, 0);
    CP_COMMIT();

    float c[4][4][4];
    #pragma unroll
    for (int mi = 0; mi < 4; mi++)
        #pragma unroll
        for (int ni = 0; ni < 4; ni++)
            #pragma unroll
            for (int q = 0; q < 4; q++) c[mi][ni][q] = 0.f;

    int m = 0, kc = 0;
    for (int it = 0; it < 16 * 13; it++) {
        int buf = it & 1;
        if (it + 1 < 16 * 13) {
            int nm = (kc == 12) ? m + 1 : m;
            int nkc = (kc == 12) ? 0 : kc + 1;
            stageA(buf ^ 1, nm, nkc);
            CP_COMMIT();
            CP_WAIT1();
        } else {
            CP_WAIT0();
        }
        __syncthreads();

        uint32_t aA = uA + buf * bufA;
        uint32_t ah[4][4];
        {
            int arow = wm + (lane & 15);
            int acol = (lane >> 4) * 8;
            #pragma unroll
            for (int mi = 0; mi < 4; mi++) {
                uint32_t off = (uint32_t)(((arow + mi * 16) * KP + acol) * 2);
                ldsm_x4(ah[mi][0], ah[mi][1], ah[mi][2], ah[mi][3], aA + off);
            }
        }
        uint32_t bh[2][4];
        {
            int r = lane & 7, seg = lane >> 3;
            int brow_in = ((seg & 2) ? 8 : 0) + r;
            int bcol = (seg & 1) * 8;
            #pragma unroll
            for (int p = 0; p < 2; p++) {
                uint32_t off = (uint32_t)(((wn + p * 16 + brow_in) * EP + kc * 16 + bcol) * 2);
                ldsm_x4(bh[p][0], bh[p][1], bh[p][2], bh[p][3], uE + off);
            }
        }
        #pragma unroll
        for (int mi = 0; mi < 4; mi++) {
            #pragma unroll
            for (int ni = 0; ni < 4; ni++) {
                int p = ni >> 1, q = (ni & 1) * 2;
                float* cc = c[mi][ni];
                mma_f16(cc[0], cc[1], cc[2], cc[3],
                        ah[mi][0], ah[mi][1], ah[mi][2], ah[mi][3], bh[p][q], bh[p][q + 1]);
            }
        }

        if (kc == 12) {
            // epilogue for this m-tile
            #pragma unroll
            for (int mi = 0; mi < 4; mi++) {
                #pragma unroll
                for (int ni = 0; ni < 4; ni++) {
                    int r  = m * 128 + wm + mi * 16 + (lane >> 2);
                    int cg = e0 + wn + ni * 8 + (lane & 3) * 2;
                    float* cc = c[mi][ni];
                    if (cg < NENT) {
                        *(float2*)&out[(long)r * NENT + cg]       = make_float2(cc[0], cc[1]);
                        *(float2*)&out[(long)(r + 8) * NENT + cg] = make_float2(cc[2], cc[3]);
                    }
                    cc[0] = cc[1] = cc[2] = cc[3] = 0.f;
                }
            }
            kc = 0; m++;
        } else {
            kc++;
        }
        __syncthreads();
    }
}

// ---------------- K9: reg outputs + T passthrough ----------------
__global__ void k_tail(const float* __restrict__ T, float* __restrict__ out) {
    int i = blockIdx.x * blockDim.x + threadIdx.x;
    if (i < 5) out[REG_OFF + i] = powf(g_acc[i], 0.25f);
    if (i < NTS * DIMV) out[T_OFF + i] = T[i];
}

// ---------------- launch ----------------
extern "C" void kernel_launch(void* const* d_in, const int* in_sizes, int n_in,
                              void* d_out, int out_size) {
    const int*   x    = (const int*)d_in[0];
    const float* E    = (const float*)d_in[1];
    const float* R    = (const float*)d_in[2];
    const float* RnoT = (const float*)d_in[3];
    const float* T    = (const float*)d_in[4];
    const float* W    = (const float*)d_in[5];
    const float* g0   = (const float*)d_in[6];
    const float* be0  = (const float*)d_in[7];
    const float* g1   = (const float*)d_in[8];
    const float* be1  = (const float*)d_in[9];
    float* out = (float*)d_out;

    cudaFuncSetAttribute(k_pred, cudaFuncAttributeMaxDynamicSharedMemorySize, PRED_SMEM);

    k_init<<<512, 256>>>(x);
    k_ehalf<<<(int)(((long)NEPAD * 26 + 255) / 256), 256>>>(E);
    k_whalf<<<dim3(1250, 8), 256>>>(W);
    k_gather<<<BSZ, 256>>>(x, E, R, RnoT, T);
    k_bn0<<<DIMV, 256>>>(g0, be0);
    k_hgemm<<<dim3(16, 4, 10), 256>>>();
    k_bn1<<<DIMV, 256>>>(g1, be1);
    k_pred<<<782, 256, PRED_SMEM>>>(out);
    k_tail<<<320, 256>>>(T, out);
}